// round 7
// baseline (speedup 1.0000x reference)
#include <cuda_runtime.h>
#include <cuda_bf16.h>
#include <cstdint>
#include <cstddef>

// ===================== portable tensor-core helpers (sm_80+) ================
__device__ __forceinline__ uint32_t smem_u32(const void* p) {
    uint32_t a;
    asm("{ .reg .u64 t; cvta.to.shared.u64 t, %1; cvt.u32.u64 %0, t; }"
        : "=r"(a) : "l"(p));
    return a;
}
#define CP16(sm, gp) \
    asm volatile("cp.async.cg.shared.global [%0], [%1], 16;" :: "r"(sm), "l"(gp))
#define CP_COMMIT() asm volatile("cp.async.commit_group;" ::: "memory")
#define CP_WAIT(n)  asm volatile("cp.async.wait_group %0;" :: "n"(n) : "memory")

#define LDSM_X4(r0, r1, r2, r3, addr) \
    asm volatile("ldmatrix.sync.aligned.m8n8.x4.shared.b16 {%0,%1,%2,%3}, [%4];" \
                 : "=r"(r0), "=r"(r1), "=r"(r2), "=r"(r3) : "r"(addr))
#define MMA16816(c, a, b) \
    asm volatile("mma.sync.aligned.m16n8k16.row.col.f32.bf16.bf16.f32 " \
                 "{%0,%1,%2,%3}, {%4,%5,%6,%7}, {%8,%9}, {%0,%1,%2,%3};" \
                 : "+f"((c)[0]), "+f"((c)[1]), "+f"((c)[2]), "+f"((c)[3]) \
                 : "r"((a)[0]), "r"((a)[1]), "r"((a)[2]), "r"((a)[3]), \
                   "r"((b)[0]), "r"((b)[1]))

// ===================== scratch (bf16 split operands) ========================
// Pcat [2048][3072] : A' = [P_hi | P_hi | P_mid]           (row-major)
// Wt   [1024][3072] : B' = [W_hi | W_mid | W_hi]           (N-major)
// Qcat [32*1024][192] : per row [Q_hi | Q_hi | Q_mid]
// Rcat [16 he][2048 t][192] : per (he,t) [R_hi | R_mid | R_hi]
__device__ uint4 g_Pcat[786432];
__device__ uint4 g_Wt[393216];
__device__ uint4 g_Qcat[786432];
__device__ uint4 g_Rcat[786432];

// ===================== split kernels ========================================
__global__ void split_p(const float* __restrict__ P) {
    int idx = blockIdx.x * 256 + threadIdx.x;     // 2048 * 512
    int m = idx >> 9, kp = idx & 511;
    float2 v = make_float2(0.f, 0.f);
    if (m < 2047) v = *(const float2*)(P + (size_t)m * 1024 + 2 * kp);
    __nv_bfloat162 hi, mid;
    hi.x = __float2bfloat16(v.x); hi.y = __float2bfloat16(v.y);
    mid.x = __float2bfloat16(v.x - __bfloat162float(hi.x));
    mid.y = __float2bfloat16(v.y - __bfloat162float(hi.y));
    __nv_bfloat162* dst = (__nv_bfloat162*)g_Pcat + (size_t)m * 1536 + kp;
    dst[0] = hi; dst[512] = hi; dst[1024] = mid;
}

__global__ void split_q(const float* __restrict__ Q) {
    int idx = blockIdx.x * 256 + threadIdx.x;     // 32*1024 * 32
    int gi = idx >> 5, dp = idx & 31;
    float2 v = *(const float2*)(Q + (size_t)gi * 64 + 2 * dp);
    __nv_bfloat162 hi, mid;
    hi.x = __float2bfloat16(v.x); hi.y = __float2bfloat16(v.y);
    mid.x = __float2bfloat16(v.x - __bfloat162float(hi.x));
    mid.y = __float2bfloat16(v.y - __bfloat162float(hi.y));
    __nv_bfloat162* dst = (__nv_bfloat162*)g_Qcat + (size_t)gi * 96 + dp;
    dst[0] = hi; dst[32] = hi; dst[64] = mid;
}

__global__ void split_w(const float* __restrict__ W) {
    __shared__ float t[32][33];
    const int n0 = blockIdx.x * 32, k0 = blockIdx.y * 32;
    const int x = threadIdx.x, y = threadIdx.y;   // (32, 8)
    for (int r = 0; r < 32; r += 8)
        t[y + r][x] = W[(size_t)(k0 + y + r) * 1024 + n0 + x];
    __syncthreads();
    __nv_bfloat16* Wt = (__nv_bfloat16*)g_Wt;
    for (int r = 0; r < 32; r += 8) {
        const float v = t[x][y + r];              // W[k0+x][n0+y+r]
        const int n = n0 + y + r, k = k0 + x;
        const __nv_bfloat16 hi = __float2bfloat16(v);
        const __nv_bfloat16 mid = __float2bfloat16(v - __bfloat162float(hi));
        Wt[(size_t)n * 3072 + k] = hi;
        Wt[(size_t)n * 3072 + 1024 + k] = mid;
        Wt[(size_t)n * 3072 + 2048 + k] = hi;
    }
}

// ===================== warp-tile MMA (32x32 per warp, one k16 slice) ========
// 512 threads = 16 warps, 4x4 warp grid over a 128x128 CTA tile.
// 4 LDSM.x4 per 8 MMAs: A 2x (m16 frags), B 2x (each x4 covers an n16 span:
// regs {r0,r2} = n0-7 {k0-7,k8-15}, {r1,r3} = n8-15).
struct Frag { float c[2][4][4]; };  // [mi][ni][4]

template <int STRIDE>
__device__ __forceinline__ void mma_k16(const __nv_bfloat16* As,
                                        const __nv_bfloat16* Bs,
                                        int wm, int wn, int lane, int k16,
                                        Frag& f) {
    uint32_t a[2][4], b[4][2];
#pragma unroll
    for (int mi = 0; mi < 2; ++mi) {
        const uint32_t ad = smem_u32(
            As + (wm + mi * 16 + (lane & 15)) * STRIDE + k16 + ((lane >> 4) << 3));
        LDSM_X4(a[mi][0], a[mi][1], a[mi][2], a[mi][3], ad);
    }
#pragma unroll
    for (int nh = 0; nh < 2; ++nh) {
        uint32_t r0, r1, r2, r3;
        const uint32_t bd = smem_u32(
            Bs + (wn + nh * 16 + (lane & 15)) * STRIDE + k16 + ((lane >> 4) << 3));
        LDSM_X4(r0, r1, r2, r3, bd);
        b[nh * 2][0] = r0;     b[nh * 2][1] = r2;
        b[nh * 2 + 1][0] = r1; b[nh * 2 + 1][1] = r3;
    }
#pragma unroll
    for (int mi = 0; mi < 2; ++mi)
#pragma unroll
        for (int ni = 0; ni < 4; ++ni)
            MMA16816(f.c[mi][ni], a[mi], b[ni]);
}

// ===================== GEMM1: R = P @ W  (M=2048,N=1024,K'=3072) ============
// 4-stage cp.async ring, one __syncthreads per 32-K step, 512 threads.
#define G1_STAGE_ELEMS 10240       // A 128x40 + B 128x40 bf16
#define G1_STAGE_BYTES 20480
#define NSTAGE 4

__global__ __launch_bounds__(512) void gemm1_mma() {
    extern __shared__ __nv_bfloat16 sm[];
    const int tid = threadIdx.x, lane = tid & 31, wid = tid >> 5;
    const int wm = (wid >> 2) << 5, wn = (wid & 3) << 5;
    const int m0 = blockIdx.y << 7, n0 = blockIdx.x << 7;

    const __nv_bfloat16* Ag = (const __nv_bfloat16*)g_Pcat;
    const __nv_bfloat16* Bg = (const __nv_bfloat16*)g_Wt;
    __nv_bfloat16* Rc = (__nv_bfloat16*)g_Rcat;

    // 512 threads: exactly one CP16 per operand per stage
    const int lrow = tid >> 2, lch = (tid & 3) << 3;
    const uint32_t sA = smem_u32(sm) + (uint32_t)(lrow * 40 + lch) * 2;
    const uint32_t sB = sA + G1_STAGE_BYTES / 2;
    const __nv_bfloat16* gA = Ag + (size_t)(m0 + lrow) * 3072 + lch;
    const __nv_bfloat16* gB = Bg + (size_t)(n0 + lrow) * 3072 + lch;

    const int NK = 96;
#pragma unroll
    for (int s = 0; s < 3; ++s) {
        const uint32_t off = (uint32_t)(s * G1_STAGE_BYTES);
        const size_t go = (size_t)s * 32;
        CP16(sA + off, gA + go);
        CP16(sB + off, gB + go);
        CP_COMMIT();
    }

    Frag f;
#pragma unroll
    for (int mi = 0; mi < 2; ++mi)
#pragma unroll
        for (int ni = 0; ni < 4; ++ni)
#pragma unroll
            for (int r = 0; r < 4; ++r) f.c[mi][ni][r] = 0.f;

    for (int kk = 0; kk < NK; ++kk) {
        CP_WAIT(2);                 // stage kk landed
        __syncthreads();            // all warps done reading slot (kk+3)%4
        if (kk + 3 < NK) {
            const uint32_t off = (uint32_t)(((kk + 3) & (NSTAGE - 1)) * G1_STAGE_BYTES);
            const size_t go = (size_t)(kk + 3) * 32;
            CP16(sA + off, gA + go);
            CP16(sB + off, gB + go);
        }
        CP_COMMIT();
        const __nv_bfloat16* As = sm + (kk & (NSTAGE - 1)) * G1_STAGE_ELEMS;
        mma_k16<40>(As, As + 5120, wm, wn, lane, 0, f);
        mma_k16<40>(As, As + 5120, wm, wn, lane, 16, f);
    }

    // epilogue: fp32 accum -> bf16 hi/mid -> Rcat[he][m][split][64]
#pragma unroll
    for (int mi = 0; mi < 2; ++mi)
#pragma unroll
        for (int ni = 0; ni < 4; ++ni)
#pragma unroll
            for (int r = 0; r < 2; ++r) {
                const int m = m0 + wm + mi * 16 + (lane >> 2) + r * 8;
                const int n = n0 + wn + ni * 8 + ((lane & 3) << 1);
                const float x0 = f.c[mi][ni][r * 2];
                const float x1 = f.c[mi][ni][r * 2 + 1];
                __nv_bfloat162 hi, mid;
                hi.x = __float2bfloat16(x0); hi.y = __float2bfloat16(x1);
                mid.x = __float2bfloat16(x0 - __bfloat162float(hi.x));
                mid.y = __float2bfloat16(x1 - __bfloat162float(hi.y));
                const int he = n >> 6, d = n & 63;
                __nv_bfloat16* p = Rc + ((size_t)(he * 2048 + m)) * 192 + d;
                *(__nv_bfloat162*)(p)       = hi;
                *(__nv_bfloat162*)(p + 64)  = mid;
                *(__nv_bfloat162*)(p + 128) = hi;
            }
}

// ===================== GEMM2: banded score, diagonal form ===================
// out[g, i, i+c] = sum Qcat[g,i,:] . Rcat[he, 1023+c, :]   (K'=192)
// K fully smem-resident: one cp.async burst, ONE barrier, 96 MMAs/warp burst.
// __launch_bounds__(512, 2): cap regs at 64 so 2 CTAs co-reside per SM and
// the 2nd CTA's cp.async burst overlaps the 1st CTA's MMA burst.
#define G2_STRIDE 200               // 192 + 8 pad (conflict-free ldmatrix)
#define G2_ARR    25600             // 128 * 200 bf16 elems

__global__ __launch_bounds__(512, 2) void gemm2_mma(float* __restrict__ out) {
    extern __shared__ __nv_bfloat16 sm[];
    const int tid = threadIdx.x, lane = tid & 31, wid = tid >> 5;
    const int wm = (wid >> 2) << 5, wn = (wid & 3) << 5;
    const int g = blockIdx.z, he = g >> 1;
    const int i0 = blockIdx.y << 7;
    const int c0 = ((int)blockIdx.x - 1) * 128 - i0;
    const int t0 = 1023 + c0;

    const __nv_bfloat16* Ag = (const __nv_bfloat16*)g_Qcat;
    const __nv_bfloat16* Bg = (const __nv_bfloat16*)g_Rcat;

    const int lrow = tid >> 2;                  // 0..127
    const int lc0 = (tid & 3) << 3;             // 0,8,16,24
    const uint32_t sA = smem_u32(sm) + (uint32_t)(lrow * G2_STRIDE) * 2;
    const uint32_t sB = sA + (uint32_t)G2_ARR * 2;
    const __nv_bfloat16* gA = Ag + ((size_t)(g << 10) + i0 + lrow) * 192;
    int tr = t0 + lrow;                         // clamped rows feed only
    tr = tr < 0 ? 0 : (tr > 2046 ? 2046 : tr);  // never-stored columns
    const __nv_bfloat16* gB = Bg + (size_t)(he * 2048 + tr) * 192;

    // load whole K' = 192: 6 chunks of 8 per thread per operand
#pragma unroll
    for (int c = 0; c < 6; ++c) {
        const int ko = lc0 + c * 32;
        CP16(sA + (uint32_t)ko * 2, gA + ko);
        CP16(sB + (uint32_t)ko * 2, gB + ko);
    }
    CP_COMMIT();

    Frag f;
#pragma unroll
    for (int mi = 0; mi < 2; ++mi)
#pragma unroll
        for (int ni = 0; ni < 4; ++ni)
#pragma unroll
            for (int r = 0; r < 4; ++r) f.c[mi][ni][r] = 0.f;

    CP_WAIT(0);
    __syncthreads();

    const __nv_bfloat16* As = sm;
    const __nv_bfloat16* Bs = sm + G2_ARR;
#pragma unroll
    for (int ks = 0; ks < 12; ++ks)
        mma_k16<G2_STRIDE>(As, Bs, wm, wn, lane, ks << 4, f);

    // epilogue: j = i + c, guard 0 <= j < 1024; each output written once
    float* og = out + ((size_t)g << 20);
#pragma unroll
    for (int mi = 0; mi < 2; ++mi)
#pragma unroll
        for (int r = 0; r < 2; ++r) {
            const int i = i0 + wm + mi * 16 + (lane >> 2) + r * 8;
            float* orow = og + ((size_t)i << 10);
            const int jb = i + c0 + wn + ((lane & 3) << 1);
#pragma unroll
            for (int ni = 0; ni < 4; ++ni) {
                const int j0 = jb + ni * 8;
                const float x0 = f.c[mi][ni][r * 2];
                const float x1 = f.c[mi][ni][r * 2 + 1];
                if ((unsigned)j0 < 1024u)       orow[j0] = x0;
                if ((unsigned)(j0 + 1) < 1024u) orow[j0 + 1] = x1;
            }
        }
}

// ===================== launch ===============================================
extern "C" void kernel_launch(void* const* d_in, const int* in_sizes, int n_in,
                              void* d_out, int out_size) {
    const float* query = (const float*)d_in[0];
    const float* posem = (const float*)d_in[1];
    const float* dense = (const float*)d_in[2];
    float* out = (float*)d_out;
    (void)in_sizes; (void)n_in; (void)out_size;

    cudaFuncSetAttribute(gemm1_mma, cudaFuncAttributeMaxDynamicSharedMemorySize,
                         NSTAGE * G1_STAGE_BYTES);
    cudaFuncSetAttribute(gemm2_mma, cudaFuncAttributeMaxDynamicSharedMemorySize,
                         2 * G2_ARR * 2);

    split_p<<<4096, 256>>>(posem);
    split_w<<<dim3(32, 32), dim3(32, 8)>>>(dense);
    split_q<<<4096, 256>>>(query);
    gemm1_mma<<<dim3(8, 16), 512, NSTAGE * G1_STAGE_BYTES>>>();
    gemm2_mma<<<dim3(9, 8, 32), 512, 2 * G2_ARR * 2>>>(out);
}

// round 8
// speedup vs baseline: 1.0112x; 1.0112x over previous
#include <cuda_runtime.h>
#include <cuda_bf16.h>
#include <cstdint>
#include <cstddef>

// ===================== portable tensor-core helpers (sm_80+) ================
__device__ __forceinline__ uint32_t smem_u32(const void* p) {
    uint32_t a;
    asm("{ .reg .u64 t; cvta.to.shared.u64 t, %1; cvt.u32.u64 %0, t; }"
        : "=r"(a) : "l"(p));
    return a;
}
#define CP16(sm, gp) \
    asm volatile("cp.async.cg.shared.global [%0], [%1], 16;" :: "r"(sm), "l"(gp))
#define CP_COMMIT() asm volatile("cp.async.commit_group;" ::: "memory")
#define CP_WAIT(n)  asm volatile("cp.async.wait_group %0;" :: "n"(n) : "memory")

#define LDSM_X4(r0, r1, r2, r3, addr) \
    asm volatile("ldmatrix.sync.aligned.m8n8.x4.shared.b16 {%0,%1,%2,%3}, [%4];" \
                 : "=r"(r0), "=r"(r1), "=r"(r2), "=r"(r3) : "r"(addr))
#define MMA16816(c, a, b) \
    asm volatile("mma.sync.aligned.m16n8k16.row.col.f32.bf16.bf16.f32 " \
                 "{%0,%1,%2,%3}, {%4,%5,%6,%7}, {%8,%9}, {%0,%1,%2,%3};" \
                 : "+f"((c)[0]), "+f"((c)[1]), "+f"((c)[2]), "+f"((c)[3]) \
                 : "r"((a)[0]), "r"((a)[1]), "r"((a)[2]), "r"((a)[3]), \
                   "r"((b)[0]), "r"((b)[1]))

// ===================== scratch (bf16 split operands) ========================
__device__ uint4 g_Pcat[786432];   // Pcat [2048][3072] = [P_hi | P_hi | P_mid]
__device__ uint4 g_Wt[393216];     // Wt   [1024][3072] = [W_hi | W_mid | W_hi] (N-major)
__device__ uint4 g_Qcat[786432];   // Qcat [32*1024][192] = [Q_hi | Q_hi | Q_mid]
__device__ uint4 g_Rcat[786432];   // Rcat [16 he][2048 t][192] = [R_hi | R_mid | R_hi]

// ===================== split kernels ========================================
__global__ void split_p(const float* __restrict__ P) {
    int idx = blockIdx.x * 256 + threadIdx.x;     // 2048 * 512
    int m = idx >> 9, kp = idx & 511;
    float2 v = make_float2(0.f, 0.f);
    if (m < 2047) v = *(const float2*)(P + (size_t)m * 1024 + 2 * kp);
    __nv_bfloat162 hi, mid;
    hi.x = __float2bfloat16(v.x); hi.y = __float2bfloat16(v.y);
    mid.x = __float2bfloat16(v.x - __bfloat162float(hi.x));
    mid.y = __float2bfloat16(v.y - __bfloat162float(hi.y));
    __nv_bfloat162* dst = (__nv_bfloat162*)g_Pcat + (size_t)m * 1536 + kp;
    dst[0] = hi; dst[512] = hi; dst[1024] = mid;
}

__global__ void split_q(const float* __restrict__ Q) {
    int idx = blockIdx.x * 256 + threadIdx.x;     // 32*1024 * 32
    int gi = idx >> 5, dp = idx & 31;
    float2 v = *(const float2*)(Q + (size_t)gi * 64 + 2 * dp);
    __nv_bfloat162 hi, mid;
    hi.x = __float2bfloat16(v.x); hi.y = __float2bfloat16(v.y);
    mid.x = __float2bfloat16(v.x - __bfloat162float(hi.x));
    mid.y = __float2bfloat16(v.y - __bfloat162float(hi.y));
    __nv_bfloat162* dst = (__nv_bfloat162*)g_Qcat + (size_t)gi * 96 + dp;
    dst[0] = hi; dst[32] = hi; dst[64] = mid;
}

__global__ void split_w(const float* __restrict__ W) {
    __shared__ float t[32][33];
    const int n0 = blockIdx.x * 32, k0 = blockIdx.y * 32;
    const int x = threadIdx.x, y = threadIdx.y;   // (32, 8)
    for (int r = 0; r < 32; r += 8)
        t[y + r][x] = W[(size_t)(k0 + y + r) * 1024 + n0 + x];
    __syncthreads();
    __nv_bfloat16* Wt = (__nv_bfloat16*)g_Wt;
    for (int r = 0; r < 32; r += 8) {
        const float v = t[x][y + r];              // W[k0+x][n0+y+r]
        const int n = n0 + y + r, k = k0 + x;
        const __nv_bfloat16 hi = __float2bfloat16(v);
        const __nv_bfloat16 mid = __float2bfloat16(v - __bfloat162float(hi));
        Wt[(size_t)n * 3072 + k] = hi;
        Wt[(size_t)n * 3072 + 1024 + k] = mid;
        Wt[(size_t)n * 3072 + 2048 + k] = hi;
    }
}

// ===================== warp-tile fragments (32x32 per warp per k16) =========
// 512 threads = 16 warps, 4x4 warp grid over a 128x128 CTA tile.
// KTile = register fragments for one k16 slice; two buffers rotate so LDSM
// of slice s+1 overlaps the 8-MMA burst of slice s.
struct Frag  { float c[2][4][4]; };               // accumulators [mi][ni][4]
struct KTile { uint32_t a[2][4]; uint32_t b[4][2]; };

template <int STRIDE>
__device__ __forceinline__ void ld_ktile(KTile& t, const __nv_bfloat16* As,
                                         const __nv_bfloat16* Bs,
                                         int wm, int wn, int lane, int k16) {
#pragma unroll
    for (int mi = 0; mi < 2; ++mi) {
        const uint32_t ad = smem_u32(
            As + (wm + mi * 16 + (lane & 15)) * STRIDE + k16 + ((lane >> 4) << 3));
        LDSM_X4(t.a[mi][0], t.a[mi][1], t.a[mi][2], t.a[mi][3], ad);
    }
#pragma unroll
    for (int nh = 0; nh < 2; ++nh) {
        uint32_t r0, r1, r2, r3;
        const uint32_t bd = smem_u32(
            Bs + (wn + nh * 16 + (lane & 15)) * STRIDE + k16 + ((lane >> 4) << 3));
        LDSM_X4(r0, r1, r2, r3, bd);
        t.b[nh * 2][0] = r0;     t.b[nh * 2][1] = r2;
        t.b[nh * 2 + 1][0] = r1; t.b[nh * 2 + 1][1] = r3;
    }
}

__device__ __forceinline__ void mma_ktile(const KTile& t, Frag& f) {
#pragma unroll
    for (int mi = 0; mi < 2; ++mi)
#pragma unroll
        for (int ni = 0; ni < 4; ++ni)
            MMA16816(f.c[mi][ni], t.a[mi], t.b[ni]);
}

// ===================== GEMM1: R = P @ W  (M=2048,N=1024,K'=3072) ============
// BK=64 per stage (4 k16 slices), 3-stage cp.async ring, ONE barrier per
// 64-K step (48 total), register-double-buffered fragments.
#define G1_STRIDE 72                       // 64 + 8 pad (144B = 9*16B, cf-free)
#define G1_OP_ELEMS (128 * G1_STRIDE)      // 9216 elems per operand
#define G1_STAGE_ELEMS (2 * G1_OP_ELEMS)   // 18432 elems (A+B)
#define G1_STAGE_BYTES (G1_STAGE_ELEMS * 2)

__global__ __launch_bounds__(512) void gemm1_mma() {
    extern __shared__ __nv_bfloat16 sm[];
    const int tid = threadIdx.x, lane = tid & 31, wid = tid >> 5;
    const int wm = (wid >> 2) << 5, wn = (wid & 3) << 5;
    const int m0 = blockIdx.y << 7, n0 = blockIdx.x << 7;

    const __nv_bfloat16* Ag = (const __nv_bfloat16*)g_Pcat;
    const __nv_bfloat16* Bg = (const __nv_bfloat16*)g_Wt;
    __nv_bfloat16* Rc = (__nv_bfloat16*)g_Rcat;

    // per stage: 128 rows x 64 elems per operand; 2 CP16/thread/operand
    const int lrow = tid >> 2, lch = (tid & 3) << 3;
    const uint32_t sA = smem_u32(sm) + (uint32_t)(lrow * G1_STRIDE + lch) * 2;
    const uint32_t sB = sA + (uint32_t)G1_OP_ELEMS * 2;
    const __nv_bfloat16* gA = Ag + (size_t)(m0 + lrow) * 3072 + lch;
    const __nv_bfloat16* gB = Bg + (size_t)(n0 + lrow) * 3072 + lch;

    const int NK = 48;
#pragma unroll
    for (int s = 0; s < 2; ++s) {
        const uint32_t off = (uint32_t)(s * G1_STAGE_BYTES);
        const size_t go = (size_t)s * 64;
        CP16(sA + off, gA + go); CP16(sA + off + 64, gA + go + 32);
        CP16(sB + off, gB + go); CP16(sB + off + 64, gB + go + 32);
        CP_COMMIT();
    }

    Frag f;
#pragma unroll
    for (int mi = 0; mi < 2; ++mi)
#pragma unroll
        for (int ni = 0; ni < 4; ++ni)
#pragma unroll
            for (int r = 0; r < 4; ++r) f.c[mi][ni][r] = 0.f;

    int rs = 0, ws = 2;                     // read slot, write slot (mod 3)
    for (int kk = 0; kk < NK; ++kk) {
        CP_WAIT(1);                         // stage kk landed
        __syncthreads();                    // all warps done reading slot ws
        if (kk + 2 < NK) {
            const uint32_t off = (uint32_t)(ws * G1_STAGE_BYTES);
            const size_t go = (size_t)(kk + 2) * 64;
            CP16(sA + off, gA + go); CP16(sA + off + 64, gA + go + 32);
            CP16(sB + off, gB + go); CP16(sB + off + 64, gB + go + 32);
        }
        CP_COMMIT();
        const __nv_bfloat16* As = sm + rs * G1_STAGE_ELEMS;
        const __nv_bfloat16* Bs = As + G1_OP_ELEMS;
        KTile t0, t1;
        ld_ktile<G1_STRIDE>(t0, As, Bs, wm, wn, lane, 0);
        ld_ktile<G1_STRIDE>(t1, As, Bs, wm, wn, lane, 16);
        mma_ktile(t0, f);
        ld_ktile<G1_STRIDE>(t0, As, Bs, wm, wn, lane, 32);
        mma_ktile(t1, f);
        ld_ktile<G1_STRIDE>(t1, As, Bs, wm, wn, lane, 48);
        mma_ktile(t0, f);
        mma_ktile(t1, f);
        rs = rs == 2 ? 0 : rs + 1;
        ws = ws == 2 ? 0 : ws + 1;
    }

    // epilogue: fp32 accum -> bf16 hi/mid -> Rcat[he][m][split][64]
#pragma unroll
    for (int mi = 0; mi < 2; ++mi)
#pragma unroll
        for (int ni = 0; ni < 4; ++ni)
#pragma unroll
            for (int r = 0; r < 2; ++r) {
                const int m = m0 + wm + mi * 16 + (lane >> 2) + r * 8;
                const int n = n0 + wn + ni * 8 + ((lane & 3) << 1);
                const float x0 = f.c[mi][ni][r * 2];
                const float x1 = f.c[mi][ni][r * 2 + 1];
                __nv_bfloat162 hi, mid;
                hi.x = __float2bfloat16(x0); hi.y = __float2bfloat16(x1);
                mid.x = __float2bfloat16(x0 - __bfloat162float(hi.x));
                mid.y = __float2bfloat16(x1 - __bfloat162float(hi.y));
                const int he = n >> 6, d = n & 63;
                __nv_bfloat16* p = Rc + ((size_t)(he * 2048 + m)) * 192 + d;
                *(__nv_bfloat162*)(p)       = hi;
                *(__nv_bfloat162*)(p + 64)  = mid;
                *(__nv_bfloat162*)(p + 128) = hi;
            }
}

// ===================== GEMM2: banded score, diagonal form ===================
// out[g, i, i+c] = sum Qcat[g,i,:] . Rcat[he, 1023+c, :]   (K'=192)
// K fully smem-resident: one cp.async burst, one barrier, register-double-
// buffered 12-slice MMA burst (96 MMAs/warp).
#define G2_STRIDE 200               // 192 + 8 pad (400B = 25*16B, cf-free)
#define G2_ARR    25600             // 128 * 200 bf16 elems

__global__ __launch_bounds__(512) void gemm2_mma(float* __restrict__ out) {
    extern __shared__ __nv_bfloat16 sm[];
    const int tid = threadIdx.x, lane = tid & 31, wid = tid >> 5;
    const int wm = (wid >> 2) << 5, wn = (wid & 3) << 5;
    const int g = blockIdx.z, he = g >> 1;
    const int i0 = blockIdx.y << 7;
    const int c0 = ((int)blockIdx.x - 1) * 128 - i0;
    const int t0 = 1023 + c0;

    const __nv_bfloat16* Ag = (const __nv_bfloat16*)g_Qcat;
    const __nv_bfloat16* Bg = (const __nv_bfloat16*)g_Rcat;

    const int lrow = tid >> 2;                  // 0..127
    const int lc0 = (tid & 3) << 3;             // 0,8,16,24
    const uint32_t sA = smem_u32(sm) + (uint32_t)(lrow * G2_STRIDE) * 2;
    const uint32_t sB = sA + (uint32_t)G2_ARR * 2;
    const __nv_bfloat16* gA = Ag + ((size_t)(g << 10) + i0 + lrow) * 192;
    int tr = t0 + lrow;                         // clamped rows feed only
    tr = tr < 0 ? 0 : (tr > 2046 ? 2046 : tr);  // never-stored columns
    const __nv_bfloat16* gB = Bg + (size_t)(he * 2048 + tr) * 192;

    // load whole K' = 192: 6 chunks of 8 per thread per operand
#pragma unroll
    for (int c = 0; c < 6; ++c) {
        const int ko = lc0 + c * 32;
        CP16(sA + (uint32_t)ko * 2, gA + ko);
        CP16(sB + (uint32_t)ko * 2, gB + ko);
    }
    CP_COMMIT();

    Frag f;
#pragma unroll
    for (int mi = 0; mi < 2; ++mi)
#pragma unroll
        for (int ni = 0; ni < 4; ++ni)
#pragma unroll
            for (int r = 0; r < 4; ++r) f.c[mi][ni][r] = 0.f;

    CP_WAIT(0);
    __syncthreads();

    const __nv_bfloat16* As = sm;
    const __nv_bfloat16* Bs = sm + G2_ARR;
    KTile t0f, t1f;
    ld_ktile<G2_STRIDE>(t0f, As, Bs, wm, wn, lane, 0);
#pragma unroll
    for (int ks = 0; ks < 12; ks += 2) {
        if (ks + 1 < 12) ld_ktile<G2_STRIDE>(t1f, As, Bs, wm, wn, lane, (ks + 1) << 4);
        mma_ktile(t0f, f);
        if (ks + 2 < 12) ld_ktile<G2_STRIDE>(t0f, As, Bs, wm, wn, lane, (ks + 2) << 4);
        mma_ktile(t1f, f);
    }

    // epilogue: j = i + c, guard 0 <= j < 1024; each output written once
    float* og = out + ((size_t)g << 20);
#pragma unroll
    for (int mi = 0; mi < 2; ++mi)
#pragma unroll
        for (int r = 0; r < 2; ++r) {
            const int i = i0 + wm + mi * 16 + (lane >> 2) + r * 8;
            float* orow = og + ((size_t)i << 10);
            const int jb = i + c0 + wn + ((lane & 3) << 1);
#pragma unroll
            for (int ni = 0; ni < 4; ++ni) {
                const int j0 = jb + ni * 8;
                const float x0 = f.c[mi][ni][r * 2];
                const float x1 = f.c[mi][ni][r * 2 + 1];
                if ((unsigned)j0 < 1024u)       orow[j0] = x0;
                if ((unsigned)(j0 + 1) < 1024u) orow[j0 + 1] = x1;
            }
        }
}

// ===================== launch ===============================================
extern "C" void kernel_launch(void* const* d_in, const int* in_sizes, int n_in,
                              void* d_out, int out_size) {
    const float* query = (const float*)d_in[0];
    const float* posem = (const float*)d_in[1];
    const float* dense = (const float*)d_in[2];
    float* out = (float*)d_out;
    (void)in_sizes; (void)n_in; (void)out_size;

    cudaFuncSetAttribute(gemm1_mma, cudaFuncAttributeMaxDynamicSharedMemorySize,
                         3 * G1_STAGE_BYTES);
    cudaFuncSetAttribute(gemm2_mma, cudaFuncAttributeMaxDynamicSharedMemorySize,
                         2 * G2_ARR * 2);

    split_p<<<4096, 256>>>(posem);
    split_w<<<dim3(32, 32), dim3(32, 8)>>>(dense);
    split_q<<<4096, 256>>>(query);
    gemm1_mma<<<dim3(8, 16), 512, 3 * G1_STAGE_BYTES>>>();
    gemm2_mma<<<dim3(9, 8, 32), 512, 2 * G2_ARR * 2>>>(out);
}

// round 9
// speedup vs baseline: 1.0208x; 1.0095x over previous
#include <cuda_runtime.h>
#include <cuda_bf16.h>
#include <cstdint>
#include <cstddef>

// ===================== portable tensor-core helpers (sm_80+) ================
__device__ __forceinline__ uint32_t smem_u32(const void* p) {
    uint32_t a;
    asm("{ .reg .u64 t; cvta.to.shared.u64 t, %1; cvt.u32.u64 %0, t; }"
        : "=r"(a) : "l"(p));
    return a;
}
#define CP16(sm, gp) \
    asm volatile("cp.async.cg.shared.global [%0], [%1], 16;" :: "r"(sm), "l"(gp))
#define CP_COMMIT() asm volatile("cp.async.commit_group;" ::: "memory")
#define CP_WAIT(n)  asm volatile("cp.async.wait_group %0;" :: "n"(n) : "memory")

#define LDSM_X4(r0, r1, r2, r3, addr) \
    asm volatile("ldmatrix.sync.aligned.m8n8.x4.shared.b16 {%0,%1,%2,%3}, [%4];" \
                 : "=r"(r0), "=r"(r1), "=r"(r2), "=r"(r3) : "r"(addr))
#define MMA16816(c, a, b) \
    asm volatile("mma.sync.aligned.m16n8k16.row.col.f32.bf16.bf16.f32 " \
                 "{%0,%1,%2,%3}, {%4,%5,%6,%7}, {%8,%9}, {%0,%1,%2,%3};" \
                 : "+f"((c)[0]), "+f"((c)[1]), "+f"((c)[2]), "+f"((c)[3]) \
                 : "r"((a)[0]), "r"((a)[1]), "r"((a)[2]), "r"((a)[3]), \
                   "r"((b)[0]), "r"((b)[1]))

// ===================== scratch (bf16 split operands) ========================
__device__ uint4 g_Pcat[786432];   // Pcat [2048][3072] = [P_hi | P_hi | P_mid]
__device__ uint4 g_Wt[393216];     // Wt   [1024][3072] = [W_hi | W_mid | W_hi] (N-major)
__device__ uint4 g_Qcat[786432];   // Qcat [32*1024][192] = [Q_hi | Q_hi | Q_mid]
__device__ uint4 g_Rcat[786432];   // Rcat [16 he][2048 t][192] = [R_hi | R_mid | R_hi]

// ===================== split kernels ========================================
__global__ void split_p(const float* __restrict__ P) {
    int idx = blockIdx.x * 256 + threadIdx.x;     // 2048 * 512
    int m = idx >> 9, kp = idx & 511;
    float2 v = make_float2(0.f, 0.f);
    if (m < 2047) v = *(const float2*)(P + (size_t)m * 1024 + 2 * kp);
    __nv_bfloat162 hi, mid;
    hi.x = __float2bfloat16(v.x); hi.y = __float2bfloat16(v.y);
    mid.x = __float2bfloat16(v.x - __bfloat162float(hi.x));
    mid.y = __float2bfloat16(v.y - __bfloat162float(hi.y));
    __nv_bfloat162* dst = (__nv_bfloat162*)g_Pcat + (size_t)m * 1536 + kp;
    dst[0] = hi; dst[512] = hi; dst[1024] = mid;
}

__global__ void split_q(const float* __restrict__ Q) {
    int idx = blockIdx.x * 256 + threadIdx.x;     // 32*1024 * 32
    int gi = idx >> 5, dp = idx & 31;
    float2 v = *(const float2*)(Q + (size_t)gi * 64 + 2 * dp);
    __nv_bfloat162 hi, mid;
    hi.x = __float2bfloat16(v.x); hi.y = __float2bfloat16(v.y);
    mid.x = __float2bfloat16(v.x - __bfloat162float(hi.x));
    mid.y = __float2bfloat16(v.y - __bfloat162float(hi.y));
    __nv_bfloat162* dst = (__nv_bfloat162*)g_Qcat + (size_t)gi * 96 + dp;
    dst[0] = hi; dst[32] = hi; dst[64] = mid;
}

__global__ void split_w(const float* __restrict__ W) {
    __shared__ float t[32][33];
    const int n0 = blockIdx.x * 32, k0 = blockIdx.y * 32;
    const int x = threadIdx.x, y = threadIdx.y;   // (32, 8)
    for (int r = 0; r < 32; r += 8)
        t[y + r][x] = W[(size_t)(k0 + y + r) * 1024 + n0 + x];
    __syncthreads();
    __nv_bfloat16* Wt = (__nv_bfloat16*)g_Wt;
    for (int r = 0; r < 32; r += 8) {
        const float v = t[x][y + r];              // W[k0+x][n0+y+r]
        const int n = n0 + y + r, k = k0 + x;
        const __nv_bfloat16 hi = __float2bfloat16(v);
        const __nv_bfloat16 mid = __float2bfloat16(v - __bfloat162float(hi));
        Wt[(size_t)n * 3072 + k] = hi;
        Wt[(size_t)n * 3072 + 1024 + k] = mid;
        Wt[(size_t)n * 3072 + 2048 + k] = hi;
    }
}

// ===================== warp-tile fragments (32x32 per warp per k16) =========
// 256 threads = 8 warps, 4(m) x 2(n) warp grid over a 128x64 CTA tile.
struct Frag  { float c[2][4][4]; };               // accumulators [mi][ni][4]
struct KTile { uint32_t a[2][4]; uint32_t b[4][2]; };

template <int STRIDE>
__device__ __forceinline__ void ld_ktile(KTile& t, const __nv_bfloat16* As,
                                         const __nv_bfloat16* Bs,
                                         int wm, int wn, int lane, int k16) {
#pragma unroll
    for (int mi = 0; mi < 2; ++mi) {
        const uint32_t ad = smem_u32(
            As + (wm + mi * 16 + (lane & 15)) * STRIDE + k16 + ((lane >> 4) << 3));
        LDSM_X4(t.a[mi][0], t.a[mi][1], t.a[mi][2], t.a[mi][3], ad);
    }
#pragma unroll
    for (int nh = 0; nh < 2; ++nh) {
        uint32_t r0, r1, r2, r3;
        const uint32_t bd = smem_u32(
            Bs + (wn + nh * 16 + (lane & 15)) * STRIDE + k16 + ((lane >> 4) << 3));
        LDSM_X4(r0, r1, r2, r3, bd);
        t.b[nh * 2][0] = r0;     t.b[nh * 2][1] = r2;
        t.b[nh * 2 + 1][0] = r1; t.b[nh * 2 + 1][1] = r3;
    }
}

__device__ __forceinline__ void mma_ktile(const KTile& t, Frag& f) {
#pragma unroll
    for (int mi = 0; mi < 2; ++mi)
#pragma unroll
        for (int ni = 0; ni < 4; ++ni)
            MMA16816(f.c[mi][ni], t.a[mi], t.b[ni]);
}

// ===================== GEMM1: R = P @ W  (M=2048,N=1024,K'=3072) ============
// CTA tile 128(M) x 64(N), BK=64, 3-stage cp.async ring, 256 threads.
// smem/CTA = 81KB -> 2 CTAs/SM; grid 256 CTAs covers all 148 SMs in 1 wave.
#define G1_STRIDE 72                        // 64 + 8 pad (144B, cf-free ldmatrix)
#define G1_A_ELEMS (128 * G1_STRIDE)        // 9216
#define G1_B_ELEMS (64 * G1_STRIDE)         // 4608
#define G1_STAGE_ELEMS (G1_A_ELEMS + G1_B_ELEMS)
#define G1_STAGE_BYTES (G1_STAGE_ELEMS * 2) // 27648

__global__ __launch_bounds__(256) void gemm1_mma() {
    extern __shared__ __nv_bfloat16 sm[];
    const int tid = threadIdx.x, lane = tid & 31, wid = tid >> 5;
    const int wm = (wid >> 1) << 5, wn = (wid & 1) << 5;
    const int m0 = blockIdx.y << 7, n0 = blockIdx.x << 6;

    const __nv_bfloat16* Ag = (const __nv_bfloat16*)g_Pcat + (size_t)m0 * 3072;
    const __nv_bfloat16* Bg = (const __nv_bfloat16*)g_Wt + (size_t)n0 * 3072;
    __nv_bfloat16* Rc = (__nv_bfloat16*)g_Rcat;

    const uint32_t smA = smem_u32(sm);

    // stage loader: A 128x64 (4 iters), B 64x64 (2 iters); chunks of 8 elems
#define G1_LOAD_STAGE(slot, kglob)                                            \
    do {                                                                      \
        const uint32_t _sb = smA + (uint32_t)(slot) * G1_STAGE_BYTES;         \
        _Pragma("unroll")                                                     \
        for (int r = 0; r < 4; ++r) {                                         \
            const int idx = r * 256 + tid;                                    \
            const int row = idx >> 3, ko = (idx & 7) << 3;                    \
            CP16(_sb + (uint32_t)(row * G1_STRIDE + ko) * 2,                  \
                 Ag + (size_t)row * 3072 + (kglob) + ko);                     \
        }                                                                     \
        _Pragma("unroll")                                                     \
        for (int r = 0; r < 2; ++r) {                                         \
            const int idx = r * 256 + tid;                                    \
            const int row = idx >> 3, ko = (idx & 7) << 3;                    \
            CP16(_sb + (uint32_t)(G1_A_ELEMS + row * G1_STRIDE + ko) * 2,     \
                 Bg + (size_t)row * 3072 + (kglob) + ko);                     \
        }                                                                     \
    } while (0)

    const int NK = 48;
    G1_LOAD_STAGE(0, 0);   CP_COMMIT();
    G1_LOAD_STAGE(1, 64);  CP_COMMIT();

    Frag f;
#pragma unroll
    for (int mi = 0; mi < 2; ++mi)
#pragma unroll
        for (int ni = 0; ni < 4; ++ni)
#pragma unroll
            for (int r = 0; r < 4; ++r) f.c[mi][ni][r] = 0.f;

    int rs = 0, ws = 2;                     // read slot, write slot (mod 3)
    for (int kk = 0; kk < NK; ++kk) {
        CP_WAIT(1);                         // stage kk landed
        __syncthreads();                    // all warps done reading slot ws
        if (kk + 2 < NK) G1_LOAD_STAGE(ws, (kk + 2) * 64);
        CP_COMMIT();                        // unconditional: keeps numbering
        const __nv_bfloat16* As = sm + rs * G1_STAGE_ELEMS;
        const __nv_bfloat16* Bs = As + G1_A_ELEMS;
        KTile t0, t1;
        ld_ktile<G1_STRIDE>(t0, As, Bs, wm, wn, lane, 0);
        ld_ktile<G1_STRIDE>(t1, As, Bs, wm, wn, lane, 16);
        mma_ktile(t0, f);
        ld_ktile<G1_STRIDE>(t0, As, Bs, wm, wn, lane, 32);
        mma_ktile(t1, f);
        ld_ktile<G1_STRIDE>(t1, As, Bs, wm, wn, lane, 48);
        mma_ktile(t0, f);
        mma_ktile(t1, f);
        rs = rs == 2 ? 0 : rs + 1;
        ws = ws == 2 ? 0 : ws + 1;
    }

    // epilogue: fp32 accum -> bf16 hi/mid -> Rcat[he][m][split][64]
#pragma unroll
    for (int mi = 0; mi < 2; ++mi)
#pragma unroll
        for (int ni = 0; ni < 4; ++ni)
#pragma unroll
            for (int r = 0; r < 2; ++r) {
                const int m = m0 + wm + mi * 16 + (lane >> 2) + r * 8;
                const int n = n0 + wn + ni * 8 + ((lane & 3) << 1);
                const float x0 = f.c[mi][ni][r * 2];
                const float x1 = f.c[mi][ni][r * 2 + 1];
                __nv_bfloat162 hi, mid;
                hi.x = __float2bfloat16(x0); hi.y = __float2bfloat16(x1);
                mid.x = __float2bfloat16(x0 - __bfloat162float(hi.x));
                mid.y = __float2bfloat16(x1 - __bfloat162float(hi.y));
                const int he = n >> 6, d = n & 63;
                __nv_bfloat16* p = Rc + ((size_t)(he * 2048 + m)) * 192 + d;
                *(__nv_bfloat162*)(p)       = hi;
                *(__nv_bfloat162*)(p + 64)  = mid;
                *(__nv_bfloat162*)(p + 128) = hi;
            }
}

// ===================== GEMM2: banded score, diagonal form ===================
// out[g, i, i+c] = sum Qcat[g,i,:] . Rcat[he, 1023+c, :]   (K'=192)
// CTA tile 128(i) x 64(c), K fully smem-resident (75KB -> 2 CTAs/SM),
// one cp.async burst, one barrier, reg-double-buffered 12-slice MMA burst.
#define G2_STRIDE 200               // 192 + 8 pad (400B, cf-free ldmatrix)
#define G2_A_ELEMS (128 * G2_STRIDE)  // 25600
#define G2_B_ELEMS (64 * G2_STRIDE)   // 12800
#define G2_SMEM_BYTES ((G2_A_ELEMS + G2_B_ELEMS) * 2)   // 76800

__global__ __launch_bounds__(256) void gemm2_mma(float* __restrict__ out) {
    extern __shared__ __nv_bfloat16 sm[];
    const int tid = threadIdx.x, lane = tid & 31, wid = tid >> 5;
    const int wm = (wid >> 1) << 5, wn = (wid & 1) << 5;
    const int g = blockIdx.z, he = g >> 1;
    const int i0 = blockIdx.y << 7;
    const int c0 = (int)blockIdx.x * 64 - i0 - 128;   // disjoint 64-wide c tiles
    const int t0 = 1023 + c0;

    const __nv_bfloat16* Ag = (const __nv_bfloat16*)g_Qcat
                              + ((size_t)(g << 10) + i0) * 192;
    const __nv_bfloat16* Bg = (const __nv_bfloat16*)g_Rcat
                              + (size_t)he * 2048 * 192;

    const uint32_t smA = smem_u32(sm);

    // load A 128x192 (12 iters) + B 64x192 (6 iters); 24 chunks of 8 per row
#pragma unroll
    for (int r = 0; r < 12; ++r) {
        const int idx = r * 256 + tid;
        const int row = idx / 24, ko = (idx % 24) << 3;
        CP16(smA + (uint32_t)(row * G2_STRIDE + ko) * 2,
             Ag + (size_t)row * 192 + ko);
    }
#pragma unroll
    for (int r = 0; r < 6; ++r) {
        const int idx = r * 256 + tid;
        const int row = idx / 24, ko = (idx % 24) << 3;
        int t = t0 + row;                        // clamped rows feed only
        t = t < 0 ? 0 : (t > 2046 ? 2046 : t);   // never-stored columns
        CP16(smA + (uint32_t)(G2_A_ELEMS + row * G2_STRIDE + ko) * 2,
             Bg + (size_t)t * 192 + ko);
    }
    CP_COMMIT();

    Frag f;
#pragma unroll
    for (int mi = 0; mi < 2; ++mi)
#pragma unroll
        for (int ni = 0; ni < 4; ++ni)
#pragma unroll
            for (int r = 0; r < 4; ++r) f.c[mi][ni][r] = 0.f;

    CP_WAIT(0);
    __syncthreads();

    const __nv_bfloat16* As = sm;
    const __nv_bfloat16* Bs = sm + G2_A_ELEMS;
    KTile t0f, t1f;
    ld_ktile<G2_STRIDE>(t0f, As, Bs, wm, wn, lane, 0);
#pragma unroll
    for (int ks = 0; ks < 12; ks += 2) {
        if (ks + 1 < 12) ld_ktile<G2_STRIDE>(t1f, As, Bs, wm, wn, lane, (ks + 1) << 4);
        mma_ktile(t0f, f);
        if (ks + 2 < 12) ld_ktile<G2_STRIDE>(t0f, As, Bs, wm, wn, lane, (ks + 2) << 4);
        mma_ktile(t1f, f);
    }

    // epilogue: j = i + c, guard 0 <= j < 1024; each output written once
    float* og = out + ((size_t)g << 20);
#pragma unroll
    for (int mi = 0; mi < 2; ++mi)
#pragma unroll
        for (int r = 0; r < 2; ++r) {
            const int i = i0 + wm + mi * 16 + (lane >> 2) + r * 8;
            float* orow = og + ((size_t)i << 10);
            const int jb = i + c0 + wn + ((lane & 3) << 1);
#pragma unroll
            for (int ni = 0; ni < 4; ++ni) {
                const int j0 = jb + ni * 8;
                const float x0 = f.c[mi][ni][r * 2];
                const float x1 = f.c[mi][ni][r * 2 + 1];
                if ((unsigned)j0 < 1024u)       orow[j0] = x0;
                if ((unsigned)(j0 + 1) < 1024u) orow[j0 + 1] = x1;
            }
        }
}

// ===================== launch ===============================================
extern "C" void kernel_launch(void* const* d_in, const int* in_sizes, int n_in,
                              void* d_out, int out_size) {
    const float* query = (const float*)d_in[0];
    const float* posem = (const float*)d_in[1];
    const float* dense = (const float*)d_in[2];
    float* out = (float*)d_out;
    (void)in_sizes; (void)n_in; (void)out_size;

    cudaFuncSetAttribute(gemm1_mma, cudaFuncAttributeMaxDynamicSharedMemorySize,
                         3 * G1_STAGE_BYTES);
    cudaFuncSetAttribute(gemm2_mma, cudaFuncAttributeMaxDynamicSharedMemorySize,
                         G2_SMEM_BYTES);

    split_p<<<4096, 256>>>(posem);
    split_w<<<dim3(32, 32), dim3(32, 8)>>>(dense);
    split_q<<<4096, 256>>>(query);
    gemm1_mma<<<dim3(16, 16), 256, 3 * G1_STAGE_BYTES>>>();
    gemm2_mma<<<dim3(18, 8, 32), 256, G2_SMEM_BYTES>>>(out);
}

// round 10
// speedup vs baseline: 1.3721x; 1.3441x over previous
#include <cuda_runtime.h>
#include <cuda_fp16.h>
#include <cstdint>
#include <cstddef>

// ===================== portable tensor-core helpers (sm_80+) ================
__device__ __forceinline__ uint32_t smem_u32(const void* p) {
    uint32_t a;
    asm("{ .reg .u64 t; cvta.to.shared.u64 t, %1; cvt.u32.u64 %0, t; }"
        : "=r"(a) : "l"(p));
    return a;
}
#define CP16(sm, gp) \
    asm volatile("cp.async.cg.shared.global [%0], [%1], 16;" :: "r"(sm), "l"(gp))
#define CP_COMMIT() asm volatile("cp.async.commit_group;" ::: "memory")
#define CP_WAIT(n)  asm volatile("cp.async.wait_group %0;" :: "n"(n) : "memory")

#define LDSM_X4(r0, r1, r2, r3, addr) \
    asm volatile("ldmatrix.sync.aligned.m8n8.x4.shared.b16 {%0,%1,%2,%3}, [%4];" \
                 : "=r"(r0), "=r"(r1), "=r"(r2), "=r"(r3) : "r"(addr))
#define MMA16816(c, a, b) \
    asm volatile("mma.sync.aligned.m16n8k16.row.col.f32.f16.f16.f32 " \
                 "{%0,%1,%2,%3}, {%4,%5,%6,%7}, {%8,%9}, {%0,%1,%2,%3};" \
                 : "+f"((c)[0]), "+f"((c)[1]), "+f"((c)[2]), "+f"((c)[3]) \
                 : "r"((a)[0]), "r"((a)[1]), "r"((a)[2]), "r"((a)[3]), \
                   "r"((b)[0]), "r"((b)[1]))

// ===================== scratch (fp16 2-term split operands) =================
// Pcat [2048][2048] : A' = [P_hi | P_mid]  (fp16 two-term split of P)
// Wt   [1024][2048] : B' = [W_1  | W_1 ]   (fp16 round of W, N-major, dup)
// Qcat [32*1024][128] : per row [Q_hi | Q_mid]
// Rcat [16 he][2048 t][128] : per (he,t) [R_1 | R_1]  (fp16 round of R, dup)
__device__ uint4 g_Pcat[524288];
__device__ uint4 g_Wt[262144];
__device__ uint4 g_Qcat[524288];
__device__ uint4 g_Rcat[524288];

// ===================== split kernels ========================================
__global__ void split_p(const float* __restrict__ P) {
    int idx = blockIdx.x * 256 + threadIdx.x;     // 2048 rows * 512 pairs
    int m = idx >> 9, kp = idx & 511;
    float2 v = make_float2(0.f, 0.f);
    if (m < 2047) v = *(const float2*)(P + (size_t)m * 1024 + 2 * kp);
    __half2 hi, mid;
    hi.x = __float2half_rn(v.x); hi.y = __float2half_rn(v.y);
    mid.x = __float2half_rn(v.x - __half2float(hi.x));
    mid.y = __float2half_rn(v.y - __half2float(hi.y));
    __half2* dst = (__half2*)g_Pcat + (size_t)m * 1024 + kp;
    dst[0] = hi; dst[512] = mid;
}

__global__ void split_q(const float* __restrict__ Q) {
    int idx = blockIdx.x * 256 + threadIdx.x;     // 32*1024 rows * 32 pairs
    int gi = idx >> 5, dp = idx & 31;
    float2 v = *(const float2*)(Q + (size_t)gi * 64 + 2 * dp);
    __half2 hi, mid;
    hi.x = __float2half_rn(v.x); hi.y = __float2half_rn(v.y);
    mid.x = __float2half_rn(v.x - __half2float(hi.x));
    mid.y = __float2half_rn(v.y - __half2float(hi.y));
    __half2* dst = (__half2*)g_Qcat + (size_t)gi * 64 + dp;
    dst[0] = hi; dst[32] = mid;
}

__global__ void split_w(const float* __restrict__ W) {
    __shared__ float t[32][33];
    const int n0 = blockIdx.x * 32, k0 = blockIdx.y * 32;
    const int x = threadIdx.x, y = threadIdx.y;   // (32, 8)
    for (int r = 0; r < 32; r += 8)
        t[y + r][x] = W[(size_t)(k0 + y + r) * 1024 + n0 + x];
    __syncthreads();
    __half* Wt = (__half*)g_Wt;
    for (int r = 0; r < 32; r += 8) {
        const float v = t[x][y + r];              // W[k0+x][n0+y+r]
        const int n = n0 + y + r, k = k0 + x;
        const __half w1 = __float2half_rn(v);
        Wt[(size_t)n * 2048 + k] = w1;
        Wt[(size_t)n * 2048 + 1024 + k] = w1;
    }
}

// ===================== warp-tile fragments (32x32 per warp per k16) =========
// 256 threads = 8 warps, 4(m) x 2(n) warp grid over a 128x64 CTA tile.
struct Frag  { float c[2][4][4]; };               // accumulators [mi][ni][4]
struct KTile { uint32_t a[2][4]; uint32_t b[4][2]; };

template <int STRIDE>
__device__ __forceinline__ void ld_ktile(KTile& t, const __half* As,
                                         const __half* Bs,
                                         int wm, int wn, int lane, int k16) {
#pragma unroll
    for (int mi = 0; mi < 2; ++mi) {
        const uint32_t ad = smem_u32(
            As + (wm + mi * 16 + (lane & 15)) * STRIDE + k16 + ((lane >> 4) << 3));
        LDSM_X4(t.a[mi][0], t.a[mi][1], t.a[mi][2], t.a[mi][3], ad);
    }
#pragma unroll
    for (int nh = 0; nh < 2; ++nh) {
        uint32_t r0, r1, r2, r3;
        const uint32_t bd = smem_u32(
            Bs + (wn + nh * 16 + (lane & 15)) * STRIDE + k16 + ((lane >> 4) << 3));
        LDSM_X4(r0, r1, r2, r3, bd);
        t.b[nh * 2][0] = r0;     t.b[nh * 2][1] = r2;
        t.b[nh * 2 + 1][0] = r1; t.b[nh * 2 + 1][1] = r3;
    }
}

__device__ __forceinline__ void mma_ktile(const KTile& t, Frag& f) {
#pragma unroll
    for (int mi = 0; mi < 2; ++mi)
#pragma unroll
        for (int ni = 0; ni < 4; ++ni)
            MMA16816(f.c[mi][ni], t.a[mi], t.b[ni]);
}

// ===================== GEMM1: R = P @ W  (M=2048,N=1024,K'=2048) ============
// CTA tile 128(M) x 64(N), BK=64, 3-stage cp.async ring, 256 threads.
#define G1_STRIDE 72                        // 64 + 8 pad (144B, cf-free ldmatrix)
#define G1_A_ELEMS (128 * G1_STRIDE)        // 9216
#define G1_B_ELEMS (64 * G1_STRIDE)         // 4608
#define G1_STAGE_ELEMS (G1_A_ELEMS + G1_B_ELEMS)
#define G1_STAGE_BYTES (G1_STAGE_ELEMS * 2) // 27648

__global__ __launch_bounds__(256) void gemm1_mma() {
    extern __shared__ __half sm[];
    const int tid = threadIdx.x, lane = tid & 31, wid = tid >> 5;
    const int wm = (wid >> 1) << 5, wn = (wid & 1) << 5;
    const int m0 = blockIdx.y << 7, n0 = blockIdx.x << 6;

    const __half* Ag = (const __half*)g_Pcat + (size_t)m0 * 2048;
    const __half* Bg = (const __half*)g_Wt + (size_t)n0 * 2048;
    __half* Rc = (__half*)g_Rcat;

    const uint32_t smA = smem_u32(sm);

#define G1_LOAD_STAGE(slot, kglob)                                            \
    do {                                                                      \
        const uint32_t _sb = smA + (uint32_t)(slot) * G1_STAGE_BYTES;         \
        _Pragma("unroll")                                                     \
        for (int r = 0; r < 4; ++r) {                                         \
            const int idx = r * 256 + tid;                                    \
            const int row = idx >> 3, ko = (idx & 7) << 3;                    \
            CP16(_sb + (uint32_t)(row * G1_STRIDE + ko) * 2,                  \
                 Ag + (size_t)row * 2048 + (kglob) + ko);                     \
        }                                                                     \
        _Pragma("unroll")                                                     \
        for (int r = 0; r < 2; ++r) {                                         \
            const int idx = r * 256 + tid;                                    \
            const int row = idx >> 3, ko = (idx & 7) << 3;                    \
            CP16(_sb + (uint32_t)(G1_A_ELEMS + row * G1_STRIDE + ko) * 2,     \
                 Bg + (size_t)row * 2048 + (kglob) + ko);                     \
        }                                                                     \
    } while (0)

    const int NK = 32;                     // 2048 / 64
    G1_LOAD_STAGE(0, 0);   CP_COMMIT();
    G1_LOAD_STAGE(1, 64);  CP_COMMIT();

    Frag f;
#pragma unroll
    for (int mi = 0; mi < 2; ++mi)
#pragma unroll
        for (int ni = 0; ni < 4; ++ni)
#pragma unroll
            for (int r = 0; r < 4; ++r) f.c[mi][ni][r] = 0.f;

    int rs = 0, ws = 2;                     // read slot, write slot (mod 3)
    for (int kk = 0; kk < NK; ++kk) {
        CP_WAIT(1);                         // stage kk landed
        __syncthreads();                    // all warps done reading slot ws
        if (kk + 2 < NK) G1_LOAD_STAGE(ws, (kk + 2) * 64);
        CP_COMMIT();                        // unconditional: keeps numbering
        const __half* As = sm + rs * G1_STAGE_ELEMS;
        const __half* Bs = As + G1_A_ELEMS;
        KTile t0, t1;
        ld_ktile<G1_STRIDE>(t0, As, Bs, wm, wn, lane, 0);
        ld_ktile<G1_STRIDE>(t1, As, Bs, wm, wn, lane, 16);
        mma_ktile(t0, f);
        ld_ktile<G1_STRIDE>(t0, As, Bs, wm, wn, lane, 32);
        mma_ktile(t1, f);
        ld_ktile<G1_STRIDE>(t1, As, Bs, wm, wn, lane, 48);
        mma_ktile(t0, f);
        mma_ktile(t1, f);
        rs = rs == 2 ? 0 : rs + 1;
        ws = ws == 2 ? 0 : ws + 1;
    }

    // epilogue: fp32 accum -> fp16 r1 -> Rcat[he][m][r1|r1]
#pragma unroll
    for (int mi = 0; mi < 2; ++mi)
#pragma unroll
        for (int ni = 0; ni < 4; ++ni)
#pragma unroll
            for (int r = 0; r < 2; ++r) {
                const int m = m0 + wm + mi * 16 + (lane >> 2) + r * 8;
                const int n = n0 + wn + ni * 8 + ((lane & 3) << 1);
                __half2 h;
                h.x = __float2half_rn(f.c[mi][ni][r * 2]);
                h.y = __float2half_rn(f.c[mi][ni][r * 2 + 1]);
                const int he = n >> 6, d = n & 63;
                __half* p = Rc + ((size_t)(he * 2048 + m)) * 128 + d;
                *(__half2*)(p)      = h;
                *(__half2*)(p + 64) = h;
            }
}

// ===================== GEMM2: banded score, diagonal form ===================
// out[g, i, i+c] = sum Qcat[g,i,:] . Rcat[he, 1023+c, :]   (K'=128)
// CTA tile 128(i) x 64(c), K fully smem-resident (51KB -> 3 CTAs/SM),
// one cp.async burst, one barrier, reg-double-buffered 8-slice MMA burst.
#define G2_STRIDE 136               // 128 + 8 pad (272B, cf-free ldmatrix)
#define G2_A_ELEMS (128 * G2_STRIDE)  // 17408
#define G2_B_ELEMS (64 * G2_STRIDE)   // 8704
#define G2_SMEM_BYTES ((G2_A_ELEMS + G2_B_ELEMS) * 2)   // 52224

__global__ __launch_bounds__(256) void gemm2_mma(float* __restrict__ out) {
    extern __shared__ __half sm[];
    const int tid = threadIdx.x, lane = tid & 31, wid = tid >> 5;
    const int wm = (wid >> 1) << 5, wn = (wid & 1) << 5;
    const int g = blockIdx.z, he = g >> 1;
    const int i0 = blockIdx.y << 7;
    const int c0 = (int)blockIdx.x * 64 - i0 - 128;   // disjoint 64-wide c tiles
    const int t0 = 1023 + c0;

    const __half* Ag = (const __half*)g_Qcat + ((size_t)(g << 10) + i0) * 128;
    const __half* Bg = (const __half*)g_Rcat + (size_t)he * 2048 * 128;

    const uint32_t smA = smem_u32(sm);

    // load A 128x128 (8 iters) + B 64x128 (4 iters); 16 chunks of 8 per row
#pragma unroll
    for (int r = 0; r < 8; ++r) {
        const int idx = r * 256 + tid;
        const int row = idx >> 4, ko = (idx & 15) << 3;
        CP16(smA + (uint32_t)(row * G2_STRIDE + ko) * 2,
             Ag + (size_t)row * 128 + ko);
    }
#pragma unroll
    for (int r = 0; r < 4; ++r) {
        const int idx = r * 256 + tid;
        const int row = idx >> 4, ko = (idx & 15) << 3;
        int t = t0 + row;                        // clamped rows feed only
        t = t < 0 ? 0 : (t > 2046 ? 2046 : t);   // never-stored columns
        CP16(smA + (uint32_t)(G2_A_ELEMS + row * G2_STRIDE + ko) * 2,
             Bg + (size_t)t * 128 + ko);
    }
    CP_COMMIT();

    Frag f;
#pragma unroll
    for (int mi = 0; mi < 2; ++mi)
#pragma unroll
        for (int ni = 0; ni < 4; ++ni)
#pragma unroll
            for (int r = 0; r < 4; ++r) f.c[mi][ni][r] = 0.f;

    CP_WAIT(0);
    __syncthreads();

    const __half* As = sm;
    const __half* Bs = sm + G2_A_ELEMS;
    KTile t0f, t1f;
    ld_ktile<G2_STRIDE>(t0f, As, Bs, wm, wn, lane, 0);
#pragma unroll
    for (int ks = 0; ks < 8; ks += 2) {
        if (ks + 1 < 8) ld_ktile<G2_STRIDE>(t1f, As, Bs, wm, wn, lane, (ks + 1) << 4);
        mma_ktile(t0f, f);
        if (ks + 2 < 8) ld_ktile<G2_STRIDE>(t0f, As, Bs, wm, wn, lane, (ks + 2) << 4);
        mma_ktile(t1f, f);
    }

    // epilogue: j = i + c, guard 0 <= j < 1024; each output written once
    float* og = out + ((size_t)g << 20);
#pragma unroll
    for (int mi = 0; mi < 2; ++mi)
#pragma unroll
        for (int r = 0; r < 2; ++r) {
            const int i = i0 + wm + mi * 16 + (lane >> 2) + r * 8;
            float* orow = og + ((size_t)i << 10);
            const int jb = i + c0 + wn + ((lane & 3) << 1);
#pragma unroll
            for (int ni = 0; ni < 4; ++ni) {
                const int j0 = jb + ni * 8;
                const float x0 = f.c[mi][ni][r * 2];
                const float x1 = f.c[mi][ni][r * 2 + 1];
                if ((unsigned)j0 < 1024u)       orow[j0] = x0;
                if ((unsigned)(j0 + 1) < 1024u) orow[j0 + 1] = x1;
            }
        }
}

// ===================== launch ===============================================
extern "C" void kernel_launch(void* const* d_in, const int* in_sizes, int n_in,
                              void* d_out, int out_size) {
    const float* query = (const float*)d_in[0];
    const float* posem = (const float*)d_in[1];
    const float* dense = (const float*)d_in[2];
    float* out = (float*)d_out;
    (void)in_sizes; (void)n_in; (void)out_size;

    cudaFuncSetAttribute(gemm1_mma, cudaFuncAttributeMaxDynamicSharedMemorySize,
                         3 * G1_STAGE_BYTES);
    cudaFuncSetAttribute(gemm2_mma, cudaFuncAttributeMaxDynamicSharedMemorySize,
                         G2_SMEM_BYTES);

    split_p<<<4096, 256>>>(posem);
    split_w<<<dim3(32, 32), dim3(32, 8)>>>(dense);
    split_q<<<4096, 256>>>(query);
    gemm1_mma<<<dim3(16, 16), 256, 3 * G1_STAGE_BYTES>>>();
    gemm2_mma<<<dim3(18, 8, 32), 256, G2_SMEM_BYTES>>>(out);
}

// round 11
// speedup vs baseline: 1.6143x; 1.1765x over previous
#include <cuda_runtime.h>
#include <cuda_fp16.h>
#include <cstdint>
#include <cstddef>

// ===================== portable tensor-core helpers (sm_80+) ================
__device__ __forceinline__ uint32_t smem_u32(const void* p) {
    uint32_t a;
    asm("{ .reg .u64 t; cvta.to.shared.u64 t, %1; cvt.u32.u64 %0, t; }"
        : "=r"(a) : "l"(p));
    return a;
}
#define CP16(sm, gp) \
    asm volatile("cp.async.cg.shared.global [%0], [%1], 16;" :: "r"(sm), "l"(gp))
#define CP_COMMIT() asm volatile("cp.async.commit_group;" ::: "memory")
#define CP_WAIT(n)  asm volatile("cp.async.wait_group %0;" :: "n"(n) : "memory")

#define LDSM_X4(r0, r1, r2, r3, addr) \
    asm volatile("ldmatrix.sync.aligned.m8n8.x4.shared.b16 {%0,%1,%2,%3}, [%4];" \
                 : "=r"(r0), "=r"(r1), "=r"(r2), "=r"(r3) : "r"(addr))
#define MMA16816(c, a, b) \
    asm volatile("mma.sync.aligned.m16n8k16.row.col.f32.f16.f16.f32 " \
                 "{%0,%1,%2,%3}, {%4,%5,%6,%7}, {%8,%9}, {%0,%1,%2,%3};" \
                 : "+f"((c)[0]), "+f"((c)[1]), "+f"((c)[2]), "+f"((c)[3]) \
                 : "r"((a)[0]), "r"((a)[1]), "r"((a)[2]), "r"((a)[3]), \
                   "r"((b)[0]), "r"((b)[1]))

// ===================== scratch (fp16 operands) ===============================
// P1   [2048][1024] : fp16 round of P (single term)
// Wt   [1024][1024] : fp16 round of W (N-major)
// Qcat [32*1024][128] : per row [Q_hi | Q_mid]  (2-term split — accuracy anchor)
// Rcat [16 he][2048 t][128] : per (he,t) [R_1 | R_1]  (fp16 round of R, dup)
__device__ uint4 g_P1[262144];
__device__ uint4 g_Wt[131072];
__device__ uint4 g_Qcat[524288];
__device__ uint4 g_Rcat[524288];

// ===================== split kernels ========================================
__global__ void split_p(const float* __restrict__ P) {
    int idx = blockIdx.x * 256 + threadIdx.x;     // 2048 rows * 512 pairs
    int m = idx >> 9, kp = idx & 511;
    float2 v = make_float2(0.f, 0.f);
    if (m < 2047) v = *(const float2*)(P + (size_t)m * 1024 + 2 * kp);
    __half2 h;
    h.x = __float2half_rn(v.x); h.y = __float2half_rn(v.y);
    ((__half2*)g_P1)[(size_t)m * 512 + kp] = h;
}

__global__ void split_q(const float* __restrict__ Q) {
    int idx = blockIdx.x * 256 + threadIdx.x;     // 32*1024 rows * 32 pairs
    int gi = idx >> 5, dp = idx & 31;
    float2 v = *(const float2*)(Q + (size_t)gi * 64 + 2 * dp);
    __half2 hi, mid;
    hi.x = __float2half_rn(v.x); hi.y = __float2half_rn(v.y);
    mid.x = __float2half_rn(v.x - __half2float(hi.x));
    mid.y = __float2half_rn(v.y - __half2float(hi.y));
    __half2* dst = (__half2*)g_Qcat + (size_t)gi * 64 + dp;
    dst[0] = hi; dst[32] = mid;
}

__global__ void split_w(const float* __restrict__ W) {
    __shared__ float t[32][33];
    const int n0 = blockIdx.x * 32, k0 = blockIdx.y * 32;
    const int x = threadIdx.x, y = threadIdx.y;   // (32, 8)
    for (int r = 0; r < 32; r += 8)
        t[y + r][x] = W[(size_t)(k0 + y + r) * 1024 + n0 + x];
    __syncthreads();
    __half* Wt = (__half*)g_Wt;
    for (int r = 0; r < 32; r += 8) {
        const float v = t[x][y + r];              // W[k0+x][n0+y+r]
        const int n = n0 + y + r, k = k0 + x;
        Wt[(size_t)n * 1024 + k] = __float2half_rn(v);
    }
}

// ===================== warp-tile fragments (32x32 per warp per k16) =========
// 256 threads = 8 warps, 4(m) x 2(n) warp grid over a 128x64 CTA tile.
struct Frag  { float c[2][4][4]; };               // accumulators [mi][ni][4]
struct KTile { uint32_t a[2][4]; uint32_t b[4][2]; };

template <int STRIDE>
__device__ __forceinline__ void ld_ktile(KTile& t, const __half* As,
                                         const __half* Bs,
                                         int wm, int wn, int lane, int k16) {
#pragma unroll
    for (int mi = 0; mi < 2; ++mi) {
        const uint32_t ad = smem_u32(
            As + (wm + mi * 16 + (lane & 15)) * STRIDE + k16 + ((lane >> 4) << 3));
        LDSM_X4(t.a[mi][0], t.a[mi][1], t.a[mi][2], t.a[mi][3], ad);
    }
#pragma unroll
    for (int nh = 0; nh < 2; ++nh) {
        uint32_t r0, r1, r2, r3;
        const uint32_t bd = smem_u32(
            Bs + (wn + nh * 16 + (lane & 15)) * STRIDE + k16 + ((lane >> 4) << 3));
        LDSM_X4(r0, r1, r2, r3, bd);
        t.b[nh * 2][0] = r0;     t.b[nh * 2][1] = r2;
        t.b[nh * 2 + 1][0] = r1; t.b[nh * 2 + 1][1] = r3;
    }
}

__device__ __forceinline__ void mma_ktile(const KTile& t, Frag& f) {
#pragma unroll
    for (int mi = 0; mi < 2; ++mi)
#pragma unroll
        for (int ni = 0; ni < 4; ++ni)
            MMA16816(f.c[mi][ni], t.a[mi], t.b[ni]);
}

// ===================== GEMM1: R = P1 @ W1  (M=2048,N=1024,K=1024) ===========
// CTA tile 128(M) x 64(N), BK=64, 3-stage cp.async ring, 256 threads.
#define G1_STRIDE 72                        // 64 + 8 pad (144B, cf-free ldmatrix)
#define G1_A_ELEMS (128 * G1_STRIDE)        // 9216
#define G1_B_ELEMS (64 * G1_STRIDE)         // 4608
#define G1_STAGE_ELEMS (G1_A_ELEMS + G1_B_ELEMS)
#define G1_STAGE_BYTES (G1_STAGE_ELEMS * 2) // 27648

__global__ __launch_bounds__(256) void gemm1_mma() {
    extern __shared__ __half sm[];
    const int tid = threadIdx.x, lane = tid & 31, wid = tid >> 5;
    const int wm = (wid >> 1) << 5, wn = (wid & 1) << 5;
    const int m0 = blockIdx.y << 7, n0 = blockIdx.x << 6;

    const __half* Ag = (const __half*)g_P1 + (size_t)m0 * 1024;
    const __half* Bg = (const __half*)g_Wt + (size_t)n0 * 1024;
    __half* Rc = (__half*)g_Rcat;

    const uint32_t smA = smem_u32(sm);

#define G1_LOAD_STAGE(slot, kglob)                                            \
    do {                                                                      \
        const uint32_t _sb = smA + (uint32_t)(slot) * G1_STAGE_BYTES;         \
        _Pragma("unroll")                                                     \
        for (int r = 0; r < 4; ++r) {                                         \
            const int idx = r * 256 + tid;                                    \
            const int row = idx >> 3, ko = (idx & 7) << 3;                    \
            CP16(_sb + (uint32_t)(row * G1_STRIDE + ko) * 2,                  \
                 Ag + (size_t)row * 1024 + (kglob) + ko);                     \
        }                                                                     \
        _Pragma("unroll")                                                     \
        for (int r = 0; r < 2; ++r) {                                         \
            const int idx = r * 256 + tid;                                    \
            const int row = idx >> 3, ko = (idx & 7) << 3;                    \
            CP16(_sb + (uint32_t)(G1_A_ELEMS + row * G1_STRIDE + ko) * 2,     \
                 Bg + (size_t)row * 1024 + (kglob) + ko);                     \
        }                                                                     \
    } while (0)

    const int NK = 16;                     // 1024 / 64
    G1_LOAD_STAGE(0, 0);   CP_COMMIT();
    G1_LOAD_STAGE(1, 64);  CP_COMMIT();

    Frag f;
#pragma unroll
    for (int mi = 0; mi < 2; ++mi)
#pragma unroll
        for (int ni = 0; ni < 4; ++ni)
#pragma unroll
            for (int r = 0; r < 4; ++r) f.c[mi][ni][r] = 0.f;

    int rs = 0, ws = 2;                     // read slot, write slot (mod 3)
    for (int kk = 0; kk < NK; ++kk) {
        CP_WAIT(1);                         // stage kk landed
        __syncthreads();                    // all warps done reading slot ws
        if (kk + 2 < NK) G1_LOAD_STAGE(ws, (kk + 2) * 64);
        CP_COMMIT();                        // unconditional: keeps numbering
        const __half* As = sm + rs * G1_STAGE_ELEMS;
        const __half* Bs = As + G1_A_ELEMS;
        KTile t0, t1;
        ld_ktile<G1_STRIDE>(t0, As, Bs, wm, wn, lane, 0);
        ld_ktile<G1_STRIDE>(t1, As, Bs, wm, wn, lane, 16);
        mma_ktile(t0, f);
        ld_ktile<G1_STRIDE>(t0, As, Bs, wm, wn, lane, 32);
        mma_ktile(t1, f);
        ld_ktile<G1_STRIDE>(t1, As, Bs, wm, wn, lane, 48);
        mma_ktile(t0, f);
        mma_ktile(t1, f);
        rs = rs == 2 ? 0 : rs + 1;
        ws = ws == 2 ? 0 : ws + 1;
    }

    // epilogue: fp32 accum -> fp16 r1 -> Rcat[he][m][r1|r1]
#pragma unroll
    for (int mi = 0; mi < 2; ++mi)
#pragma unroll
        for (int ni = 0; ni < 4; ++ni)
#pragma unroll
            for (int r = 0; r < 2; ++r) {
                const int m = m0 + wm + mi * 16 + (lane >> 2) + r * 8;
                const int n = n0 + wn + ni * 8 + ((lane & 3) << 1);
                __half2 h;
                h.x = __float2half_rn(f.c[mi][ni][r * 2]);
                h.y = __float2half_rn(f.c[mi][ni][r * 2 + 1]);
                const int he = n >> 6, d = n & 63;
                __half* p = Rc + ((size_t)(he * 2048 + m)) * 128 + d;
                *(__half2*)(p)      = h;
                *(__half2*)(p + 64) = h;
            }
}

// ===================== GEMM2: banded score, diagonal form ===================
// out[g, i, i+c] = sum Qcat[g,i,:] . Rcat[he, 1023+c, :]   (K'=128)
// CTA tile 128(i) x 64(c), K fully smem-resident (51KB -> 3 CTAs/SM),
// one cp.async burst, one barrier, reg-double-buffered 8-slice MMA burst.
#define G2_STRIDE 136               // 128 + 8 pad (272B, cf-free ldmatrix)
#define G2_A_ELEMS (128 * G2_STRIDE)  // 17408
#define G2_B_ELEMS (64 * G2_STRIDE)   // 8704
#define G2_SMEM_BYTES ((G2_A_ELEMS + G2_B_ELEMS) * 2)   // 52224

__global__ __launch_bounds__(256) void gemm2_mma(float* __restrict__ out) {
    extern __shared__ __half sm[];
    const int tid = threadIdx.x, lane = tid & 31, wid = tid >> 5;
    const int wm = (wid >> 1) << 5, wn = (wid & 1) << 5;
    const int g = blockIdx.z, he = g >> 1;
    const int i0 = blockIdx.y << 7;
    const int c0 = (int)blockIdx.x * 64 - i0 - 128;   // disjoint 64-wide c tiles
    const int t0 = 1023 + c0;

    const __half* Ag = (const __half*)g_Qcat + ((size_t)(g << 10) + i0) * 128;
    const __half* Bg = (const __half*)g_Rcat + (size_t)he * 2048 * 128;

    const uint32_t smA = smem_u32(sm);

    // load A 128x128 (8 iters) + B 64x128 (4 iters); 16 chunks of 8 per row
#pragma unroll
    for (int r = 0; r < 8; ++r) {
        const int idx = r * 256 + tid;
        const int row = idx >> 4, ko = (idx & 15) << 3;
        CP16(smA + (uint32_t)(row * G2_STRIDE + ko) * 2,
             Ag + (size_t)row * 128 + ko);
    }
#pragma unroll
    for (int r = 0; r < 4; ++r) {
        const int idx = r * 256 + tid;
        const int row = idx >> 4, ko = (idx & 15) << 3;
        int t = t0 + row;                        // clamped rows feed only
        t = t < 0 ? 0 : (t > 2046 ? 2046 : t);   // never-stored columns
        CP16(smA + (uint32_t)(G2_A_ELEMS + row * G2_STRIDE + ko) * 2,
             Bg + (size_t)t * 128 + ko);
    }
    CP_COMMIT();

    Frag f;
#pragma unroll
    for (int mi = 0; mi < 2; ++mi)
#pragma unroll
        for (int ni = 0; ni < 4; ++ni)
#pragma unroll
            for (int r = 0; r < 4; ++r) f.c[mi][ni][r] = 0.f;

    CP_WAIT(0);
    __syncthreads();

    const __half* As = sm;
    const __half* Bs = sm + G2_A_ELEMS;
    KTile t0f, t1f;
    ld_ktile<G2_STRIDE>(t0f, As, Bs, wm, wn, lane, 0);
#pragma unroll
    for (int ks = 0; ks < 8; ks += 2) {
        if (ks + 1 < 8) ld_ktile<G2_STRIDE>(t1f, As, Bs, wm, wn, lane, (ks + 1) << 4);
        mma_ktile(t0f, f);
        if (ks + 2 < 8) ld_ktile<G2_STRIDE>(t0f, As, Bs, wm, wn, lane, (ks + 2) << 4);
        mma_ktile(t1f, f);
    }

    // epilogue: j = i + c, guard 0 <= j < 1024; each output written once
    float* og = out + ((size_t)g << 20);
#pragma unroll
    for (int mi = 0; mi < 2; ++mi)
#pragma unroll
        for (int r = 0; r < 2; ++r) {
            const int i = i0 + wm + mi * 16 + (lane >> 2) + r * 8;
            float* orow = og + ((size_t)i << 10);
            const int jb = i + c0 + wn + ((lane & 3) << 1);
#pragma unroll
            for (int ni = 0; ni < 4; ++ni) {
                const int j0 = jb + ni * 8;
                const float x0 = f.c[mi][ni][r * 2];
                const float x1 = f.c[mi][ni][r * 2 + 1];
                if ((unsigned)j0 < 1024u)       orow[j0] = x0;
                if ((unsigned)(j0 + 1) < 1024u) orow[j0 + 1] = x1;
            }
        }
}

// ===================== launch ===============================================
extern "C" void kernel_launch(void* const* d_in, const int* in_sizes, int n_in,
                              void* d_out, int out_size) {
    const float* query = (const float*)d_in[0];
    const float* posem = (const float*)d_in[1];
    const float* dense = (const float*)d_in[2];
    float* out = (float*)d_out;
    (void)in_sizes; (void)n_in; (void)out_size;

    cudaFuncSetAttribute(gemm1_mma, cudaFuncAttributeMaxDynamicSharedMemorySize,
                         3 * G1_STAGE_BYTES);
    cudaFuncSetAttribute(gemm2_mma, cudaFuncAttributeMaxDynamicSharedMemorySize,
                         G2_SMEM_BYTES);

    split_p<<<4096, 256>>>(posem);
    split_w<<<dim3(32, 32), dim3(32, 8)>>>(dense);
    split_q<<<4096, 256>>>(query);
    gemm1_mma<<<dim3(16, 16), 256, 3 * G1_STAGE_BYTES>>>();
    gemm2_mma<<<dim3(18, 8, 32), 256, G2_SMEM_BYTES>>>(out);
}

// round 12
// speedup vs baseline: 1.7943x; 1.1115x over previous
#include <cuda_runtime.h>
#include <cuda_fp16.h>
#include <cstdint>
#include <cstddef>

// ===================== portable tensor-core helpers (sm_80+) ================
__device__ __forceinline__ uint32_t smem_u32(const void* p) {
    uint32_t a;
    asm("{ .reg .u64 t; cvta.to.shared.u64 t, %1; cvt.u32.u64 %0, t; }"
        : "=r"(a) : "l"(p));
    return a;
}
#define CP16(sm, gp) \
    asm volatile("cp.async.cg.shared.global [%0], [%1], 16;" :: "r"(sm), "l"(gp))
#define CP_COMMIT() asm volatile("cp.async.commit_group;" ::: "memory")
#define CP_WAIT(n)  asm volatile("cp.async.wait_group %0;" :: "n"(n) : "memory")

#define LDSM_X4(r0, r1, r2, r3, addr) \
    asm volatile("ldmatrix.sync.aligned.m8n8.x4.shared.b16 {%0,%1,%2,%3}, [%4];" \
                 : "=r"(r0), "=r"(r1), "=r"(r2), "=r"(r3) : "r"(addr))
#define MMA16816(c, a, b) \
    asm volatile("mma.sync.aligned.m16n8k16.row.col.f32.f16.f16.f32 " \
                 "{%0,%1,%2,%3}, {%4,%5,%6,%7}, {%8,%9}, {%0,%1,%2,%3};" \
                 : "+f"((c)[0]), "+f"((c)[1]), "+f"((c)[2]), "+f"((c)[3]) \
                 : "r"((a)[0]), "r"((a)[1]), "r"((a)[2]), "r"((a)[3]), \
                   "r"((b)[0]), "r"((b)[1]))

// ===================== scratch (fp16 operands, all single-rounded) ==========
// P1 [2048][1024] : fp16 round of P
// Wt [1024][1024] : fp16 round of W (N-major)
// Q1 [32*1024][64] : fp16 round of Q
// R1 [16 he][2048 t][64] : fp16 round of R
__device__ uint4 g_P1[262144];
__device__ uint4 g_Wt[131072];
__device__ uint4 g_Q1[262144];
__device__ uint4 g_R1[262144];

// ===================== split kernels ========================================
__global__ void split_p(const float* __restrict__ P) {
    int idx = blockIdx.x * 256 + threadIdx.x;     // 2048 rows * 512 pairs
    int m = idx >> 9, kp = idx & 511;
    float2 v = make_float2(0.f, 0.f);
    if (m < 2047) v = *(const float2*)(P + (size_t)m * 1024 + 2 * kp);
    __half2 h;
    h.x = __float2half_rn(v.x); h.y = __float2half_rn(v.y);
    ((__half2*)g_P1)[(size_t)m * 512 + kp] = h;
}

__global__ void split_q(const float* __restrict__ Q) {
    int idx = blockIdx.x * 256 + threadIdx.x;     // 32*1024 rows * 32 pairs
    int gi = idx >> 5, dp = idx & 31;
    float2 v = *(const float2*)(Q + (size_t)gi * 64 + 2 * dp);
    __half2 h;
    h.x = __float2half_rn(v.x); h.y = __float2half_rn(v.y);
    ((__half2*)g_Q1)[(size_t)gi * 32 + dp] = h;
}

__global__ void split_w(const float* __restrict__ W) {
    __shared__ float t[32][33];
    const int n0 = blockIdx.x * 32, k0 = blockIdx.y * 32;
    const int x = threadIdx.x, y = threadIdx.y;   // (32, 8)
    for (int r = 0; r < 32; r += 8)
        t[y + r][x] = W[(size_t)(k0 + y + r) * 1024 + n0 + x];
    __syncthreads();
    __half* Wt = (__half*)g_Wt;
    for (int r = 0; r < 32; r += 8) {
        const float v = t[x][y + r];              // W[k0+x][n0+y+r]
        const int n = n0 + y + r, k = k0 + x;
        Wt[(size_t)n * 1024 + k] = __float2half_rn(v);
    }
}

// ===================== warp-tile fragments (32x32 per warp per k16) =========
// 256 threads = 8 warps, 4(m) x 2(n) warp grid over a 128x64 CTA tile.
struct Frag  { float c[2][4][4]; };               // accumulators [mi][ni][4]
struct KTile { uint32_t a[2][4]; uint32_t b[4][2]; };

template <int STRIDE>
__device__ __forceinline__ void ld_ktile(KTile& t, const __half* As,
                                         const __half* Bs,
                                         int wm, int wn, int lane, int k16) {
#pragma unroll
    for (int mi = 0; mi < 2; ++mi) {
        const uint32_t ad = smem_u32(
            As + (wm + mi * 16 + (lane & 15)) * STRIDE + k16 + ((lane >> 4) << 3));
        LDSM_X4(t.a[mi][0], t.a[mi][1], t.a[mi][2], t.a[mi][3], ad);
    }
#pragma unroll
    for (int nh = 0; nh < 2; ++nh) {
        uint32_t r0, r1, r2, r3;
        const uint32_t bd = smem_u32(
            Bs + (wn + nh * 16 + (lane & 15)) * STRIDE + k16 + ((lane >> 4) << 3));
        LDSM_X4(r0, r1, r2, r3, bd);
        t.b[nh * 2][0] = r0;     t.b[nh * 2][1] = r2;
        t.b[nh * 2 + 1][0] = r1; t.b[nh * 2 + 1][1] = r3;
    }
}

__device__ __forceinline__ void mma_ktile(const KTile& t, Frag& f) {
#pragma unroll
    for (int mi = 0; mi < 2; ++mi)
#pragma unroll
        for (int ni = 0; ni < 4; ++ni)
            MMA16816(f.c[mi][ni], t.a[mi], t.b[ni]);
}

// ===================== GEMM1: R = P1 @ W1  (M=2048,N=1024,K=1024) ===========
// CTA tile 128(M) x 64(N), BK=64, 3-stage cp.async ring, 256 threads.
#define G1_STRIDE 72                        // 64 + 8 pad (144B, cf-free ldmatrix)
#define G1_A_ELEMS (128 * G1_STRIDE)        // 9216
#define G1_B_ELEMS (64 * G1_STRIDE)         // 4608
#define G1_STAGE_ELEMS (G1_A_ELEMS + G1_B_ELEMS)
#define G1_STAGE_BYTES (G1_STAGE_ELEMS * 2) // 27648

__global__ __launch_bounds__(256) void gemm1_mma() {
    extern __shared__ __half sm[];
    const int tid = threadIdx.x, lane = tid & 31, wid = tid >> 5;
    const int wm = (wid >> 1) << 5, wn = (wid & 1) << 5;
    const int m0 = blockIdx.y << 7, n0 = blockIdx.x << 6;

    const __half* Ag = (const __half*)g_P1 + (size_t)m0 * 1024;
    const __half* Bg = (const __half*)g_Wt + (size_t)n0 * 1024;
    __half* Rc = (__half*)g_R1;

    const uint32_t smA = smem_u32(sm);

#define G1_LOAD_STAGE(slot, kglob)                                            \
    do {                                                                      \
        const uint32_t _sb = smA + (uint32_t)(slot) * G1_STAGE_BYTES;         \
        _Pragma("unroll")                                                     \
        for (int r = 0; r < 4; ++r) {                                         \
            const int idx = r * 256 + tid;                                    \
            const int row = idx >> 3, ko = (idx & 7) << 3;                    \
            CP16(_sb + (uint32_t)(row * G1_STRIDE + ko) * 2,                  \
                 Ag + (size_t)row * 1024 + (kglob) + ko);                     \
        }                                                                     \
        _Pragma("unroll")                                                     \
        for (int r = 0; r < 2; ++r) {                                         \
            const int idx = r * 256 + tid;                                    \
            const int row = idx >> 3, ko = (idx & 7) << 3;                    \
            CP16(_sb + (uint32_t)(G1_A_ELEMS + row * G1_STRIDE + ko) * 2,     \
                 Bg + (size_t)row * 1024 + (kglob) + ko);                     \
        }                                                                     \
    } while (0)

    const int NK = 16;                     // 1024 / 64
    G1_LOAD_STAGE(0, 0);   CP_COMMIT();
    G1_LOAD_STAGE(1, 64);  CP_COMMIT();

    Frag f;
#pragma unroll
    for (int mi = 0; mi < 2; ++mi)
#pragma unroll
        for (int ni = 0; ni < 4; ++ni)
#pragma unroll
            for (int r = 0; r < 4; ++r) f.c[mi][ni][r] = 0.f;

    int rs = 0, ws = 2;                     // read slot, write slot (mod 3)
    for (int kk = 0; kk < NK; ++kk) {
        CP_WAIT(1);                         // stage kk landed
        __syncthreads();                    // all warps done reading slot ws
        if (kk + 2 < NK) G1_LOAD_STAGE(ws, (kk + 2) * 64);
        CP_COMMIT();                        // unconditional: keeps numbering
        const __half* As = sm + rs * G1_STAGE_ELEMS;
        const __half* Bs = As + G1_A_ELEMS;
        KTile t0, t1;
        ld_ktile<G1_STRIDE>(t0, As, Bs, wm, wn, lane, 0);
        ld_ktile<G1_STRIDE>(t1, As, Bs, wm, wn, lane, 16);
        mma_ktile(t0, f);
        ld_ktile<G1_STRIDE>(t0, As, Bs, wm, wn, lane, 32);
        mma_ktile(t1, f);
        ld_ktile<G1_STRIDE>(t1, As, Bs, wm, wn, lane, 48);
        mma_ktile(t0, f);
        mma_ktile(t1, f);
        rs = rs == 2 ? 0 : rs + 1;
        ws = ws == 2 ? 0 : ws + 1;
    }

    // epilogue: fp32 accum -> fp16 -> R1[he][m][d]
#pragma unroll
    for (int mi = 0; mi < 2; ++mi)
#pragma unroll
        for (int ni = 0; ni < 4; ++ni)
#pragma unroll
            for (int r = 0; r < 2; ++r) {
                const int m = m0 + wm + mi * 16 + (lane >> 2) + r * 8;
                const int n = n0 + wn + ni * 8 + ((lane & 3) << 1);
                __half2 h;
                h.x = __float2half_rn(f.c[mi][ni][r * 2]);
                h.y = __float2half_rn(f.c[mi][ni][r * 2 + 1]);
                const int he = n >> 6, d = n & 63;
                *(__half2*)(Rc + ((size_t)(he * 2048 + m)) * 64 + d) = h;
            }
}

// ===================== GEMM2: banded score, diagonal form ===================
// out[g, i, i+c] = sum_d Q1[g,i,d] . R1[he, 1023+c, d]   (K=64)
// CTA tile 128(i) x 64(c), K fully smem-resident (27KB -> deep residency),
// one cp.async burst, one barrier, reg-double-buffered 4-slice MMA burst.
#define G2_STRIDE 72                // 64 + 8 pad (144B, cf-free ldmatrix)
#define G2_A_ELEMS (128 * G2_STRIDE)  // 9216
#define G2_B_ELEMS (64 * G2_STRIDE)   // 4608
#define G2_SMEM_BYTES ((G2_A_ELEMS + G2_B_ELEMS) * 2)   // 27648

__global__ __launch_bounds__(256) void gemm2_mma(float* __restrict__ out) {
    extern __shared__ __half sm[];
    const int tid = threadIdx.x, lane = tid & 31, wid = tid >> 5;
    const int wm = (wid >> 1) << 5, wn = (wid & 1) << 5;
    const int g = blockIdx.z, he = g >> 1;
    const int i0 = blockIdx.y << 7;
    const int c0 = (int)blockIdx.x * 64 - i0 - 128;   // disjoint 64-wide c tiles
    const int t0 = 1023 + c0;

    const __half* Ag = (const __half*)g_Q1 + ((size_t)(g << 10) + i0) * 64;
    const __half* Bg = (const __half*)g_R1 + (size_t)he * 2048 * 64;

    const uint32_t smA = smem_u32(sm);

    // load A 128x64 (4 iters) + B 64x64 (2 iters); 8 chunks of 8 per row
#pragma unroll
    for (int r = 0; r < 4; ++r) {
        const int idx = r * 256 + tid;
        const int row = idx >> 3, ko = (idx & 7) << 3;
        CP16(smA + (uint32_t)(row * G2_STRIDE + ko) * 2,
             Ag + (size_t)row * 64 + ko);
    }
#pragma unroll
    for (int r = 0; r < 2; ++r) {
        const int idx = r * 256 + tid;
        const int row = idx >> 3, ko = (idx & 7) << 3;
        int t = t0 + row;                        // clamped rows feed only
        t = t < 0 ? 0 : (t > 2046 ? 2046 : t);   // never-stored columns
        CP16(smA + (uint32_t)(G2_A_ELEMS + row * G2_STRIDE + ko) * 2,
             Bg + (size_t)t * 64 + ko);
    }
    CP_COMMIT();

    Frag f;
#pragma unroll
    for (int mi = 0; mi < 2; ++mi)
#pragma unroll
        for (int ni = 0; ni < 4; ++ni)
#pragma unroll
            for (int r = 0; r < 4; ++r) f.c[mi][ni][r] = 0.f;

    CP_WAIT(0);
    __syncthreads();

    const __half* As = sm;
    const __half* Bs = sm + G2_A_ELEMS;
    KTile t0f, t1f;
    ld_ktile<G2_STRIDE>(t0f, As, Bs, wm, wn, lane, 0);
    ld_ktile<G2_STRIDE>(t1f, As, Bs, wm, wn, lane, 16);
    mma_ktile(t0f, f);
    ld_ktile<G2_STRIDE>(t0f, As, Bs, wm, wn, lane, 32);
    mma_ktile(t1f, f);
    ld_ktile<G2_STRIDE>(t1f, As, Bs, wm, wn, lane, 48);
    mma_ktile(t0f, f);
    mma_ktile(t1f, f);

    // epilogue: j = i + c, guard 0 <= j < 1024; each output written once
    float* og = out + ((size_t)g << 20);
#pragma unroll
    for (int mi = 0; mi < 2; ++mi)
#pragma unroll
        for (int r = 0; r < 2; ++r) {
            const int i = i0 + wm + mi * 16 + (lane >> 2) + r * 8;
            float* orow = og + ((size_t)i << 10);
            const int jb = i + c0 + wn + ((lane & 3) << 1);
#pragma unroll
            for (int ni = 0; ni < 4; ++ni) {
                const int j0 = jb + ni * 8;
                const float x0 = f.c[mi][ni][r * 2];
                const float x1 = f.c[mi][ni][r * 2 + 1];
                if ((unsigned)j0 < 1024u)       orow[j0] = x0;
                if ((unsigned)(j0 + 1) < 1024u) orow[j0 + 1] = x1;
            }
        }
}

// ===================== launch ===============================================
extern "C" void kernel_launch(void* const* d_in, const int* in_sizes, int n_in,
                              void* d_out, int out_size) {
    const float* query = (const float*)d_in[0];
    const float* posem = (const float*)d_in[1];
    const float* dense = (const float*)d_in[2];
    float* out = (float*)d_out;
    (void)in_sizes; (void)n_in; (void)out_size;

    cudaFuncSetAttribute(gemm1_mma, cudaFuncAttributeMaxDynamicSharedMemorySize,
                         3 * G1_STAGE_BYTES);
    cudaFuncSetAttribute(gemm2_mma, cudaFuncAttributeMaxDynamicSharedMemorySize,
                         G2_SMEM_BYTES);

    split_p<<<4096, 256>>>(posem);
    split_w<<<dim3(32, 32), dim3(32, 8)>>>(dense);
    split_q<<<4096, 256>>>(query);
    gemm1_mma<<<dim3(16, 16), 256, 3 * G1_STAGE_BYTES>>>();
    gemm2_mma<<<dim3(18, 8, 32), 256, G2_SMEM_BYTES>>>(out);
}

// round 13
// speedup vs baseline: 1.9578x; 1.0911x over previous
#include <cuda_runtime.h>
#include <cuda_fp16.h>
#include <cstdint>
#include <cstddef>

// ===================== portable tensor-core helpers (sm_80+) ================
__device__ __forceinline__ uint32_t smem_u32(const void* p) {
    uint32_t a;
    asm("{ .reg .u64 t; cvta.to.shared.u64 t, %1; cvt.u32.u64 %0, t; }"
        : "=r"(a) : "l"(p));
    return a;
}
#define CP16(sm, gp) \
    asm volatile("cp.async.cg.shared.global [%0], [%1], 16;" :: "r"(sm), "l"(gp))
#define CP_COMMIT() asm volatile("cp.async.commit_group;" ::: "memory")
#define CP_WAIT(n)  asm volatile("cp.async.wait_group %0;" :: "n"(n) : "memory")

#define LDSM_X4(r0, r1, r2, r3, addr) \
    asm volatile("ldmatrix.sync.aligned.m8n8.x4.shared.b16 {%0,%1,%2,%3}, [%4];" \
                 : "=r"(r0), "=r"(r1), "=r"(r2), "=r"(r3) : "r"(addr))
#define MMA16816(c, a, b) \
    asm volatile("mma.sync.aligned.m16n8k16.row.col.f32.f16.f16.f32 " \
                 "{%0,%1,%2,%3}, {%4,%5,%6,%7}, {%8,%9}, {%0,%1,%2,%3};" \
                 : "+f"((c)[0]), "+f"((c)[1]), "+f"((c)[2]), "+f"((c)[3]) \
                 : "r"((a)[0]), "r"((a)[1]), "r"((a)[2]), "r"((a)[3]), \
                   "r"((b)[0]), "r"((b)[1]))

// ===================== scratch (fp16 operands, all single-rounded) ==========
// P1 [2048][1024] : fp16 round of P
// Wt [1024][1024] : fp16 round of W (N-major)
// Q1 [32*1024][64] : fp16 round of Q
// R1 [16 he][2048 t][64] : fp16 round of R
__device__ uint4 g_P1[262144];
__device__ uint4 g_Wt[131072];
__device__ uint4 g_Q1[262144];
__device__ uint4 g_R1[262144];

// ===================== split kernels ========================================
// split_p + split_q merged: both elementwise fp32 -> fp16 rounds.
__global__ void split_pq(const float* __restrict__ P,
                         const float* __restrict__ Q) {
    int idx = blockIdx.x * 256 + threadIdx.x;     // 2M total
    if (idx < 1048576) {                          // P: 2048 rows * 512 pairs
        int m = idx >> 9, kp = idx & 511;
        float2 v = make_float2(0.f, 0.f);
        if (m < 2047) v = *(const float2*)(P + (size_t)m * 1024 + 2 * kp);
        __half2 h;
        h.x = __float2half_rn(v.x); h.y = __float2half_rn(v.y);
        ((__half2*)g_P1)[(size_t)m * 512 + kp] = h;
    } else {                                      // Q: 32768 rows * 32 pairs
        int q = idx - 1048576;
        int gi = q >> 5, dp = q & 31;
        float2 v = *(const float2*)(Q + (size_t)gi * 64 + 2 * dp);
        __half2 h;
        h.x = __float2half_rn(v.x); h.y = __float2half_rn(v.y);
        ((__half2*)g_Q1)[(size_t)gi * 32 + dp] = h;
    }
}

__global__ void split_w(const float* __restrict__ W) {
    __shared__ float t[32][33];
    const int n0 = blockIdx.x * 32, k0 = blockIdx.y * 32;
    const int x = threadIdx.x, y = threadIdx.y;   // (32, 8)
    for (int r = 0; r < 32; r += 8)
        t[y + r][x] = W[(size_t)(k0 + y + r) * 1024 + n0 + x];
    __syncthreads();
    __half* Wt = (__half*)g_Wt;
    for (int r = 0; r < 32; r += 8) {
        const float v = t[x][y + r];              // W[k0+x][n0+y+r]
        const int n = n0 + y + r, k = k0 + x;
        Wt[(size_t)n * 1024 + k] = __float2half_rn(v);
    }
}

// ===================== warp-tile fragments (32x32 per warp per k16) =========
// 256 threads = 8 warps, 4(m) x 2(n) warp grid over a 128x64 CTA tile.
struct Frag  { float c[2][4][4]; };               // accumulators [mi][ni][4]
struct KTile { uint32_t a[2][4]; uint32_t b[4][2]; };

template <int STRIDE>
__device__ __forceinline__ void ld_ktile(KTile& t, const __half* As,
                                         const __half* Bs,
                                         int wm, int wn, int lane, int k16) {
#pragma unroll
    for (int mi = 0; mi < 2; ++mi) {
        const uint32_t ad = smem_u32(
            As + (wm + mi * 16 + (lane & 15)) * STRIDE + k16 + ((lane >> 4) << 3));
        LDSM_X4(t.a[mi][0], t.a[mi][1], t.a[mi][2], t.a[mi][3], ad);
    }
#pragma unroll
    for (int nh = 0; nh < 2; ++nh) {
        uint32_t r0, r1, r2, r3;
        const uint32_t bd = smem_u32(
            Bs + (wn + nh * 16 + (lane & 15)) * STRIDE + k16 + ((lane >> 4) << 3));
        LDSM_X4(r0, r1, r2, r3, bd);
        t.b[nh * 2][0] = r0;     t.b[nh * 2][1] = r2;
        t.b[nh * 2 + 1][0] = r1; t.b[nh * 2 + 1][1] = r3;
    }
}

__device__ __forceinline__ void mma_ktile(const KTile& t, Frag& f) {
#pragma unroll
    for (int mi = 0; mi < 2; ++mi)
#pragma unroll
        for (int ni = 0; ni < 4; ++ni)
            MMA16816(f.c[mi][ni], t.a[mi], t.b[ni]);
}

// ===================== GEMM1: R = P1 @ W1  (M=2048,N=1024,K=1024) ===========
// CTA tile 128(M) x 64(N), BK=64, 3-stage cp.async ring, 256 threads.
#define G1_STRIDE 72                        // 64 + 8 pad (144B, cf-free ldmatrix)
#define G1_A_ELEMS (128 * G1_STRIDE)        // 9216
#define G1_B_ELEMS (64 * G1_STRIDE)         // 4608
#define G1_STAGE_ELEMS (G1_A_ELEMS + G1_B_ELEMS)
#define G1_STAGE_BYTES (G1_STAGE_ELEMS * 2) // 27648

__global__ __launch_bounds__(256) void gemm1_mma() {
    extern __shared__ __half sm[];
    const int tid = threadIdx.x, lane = tid & 31, wid = tid >> 5;
    const int wm = (wid >> 1) << 5, wn = (wid & 1) << 5;
    const int m0 = blockIdx.y << 7, n0 = blockIdx.x << 6;

    const __half* Ag = (const __half*)g_P1 + (size_t)m0 * 1024;
    const __half* Bg = (const __half*)g_Wt + (size_t)n0 * 1024;
    __half* Rc = (__half*)g_R1;

    const uint32_t smA = smem_u32(sm);

#define G1_LOAD_STAGE(slot, kglob)                                            \
    do {                                                                      \
        const uint32_t _sb = smA + (uint32_t)(slot) * G1_STAGE_BYTES;         \
        _Pragma("unroll")                                                     \
        for (int r = 0; r < 4; ++r) {                                         \
            const int idx = r * 256 + tid;                                    \
            const int row = idx >> 3, ko = (idx & 7) << 3;                    \
            CP16(_sb + (uint32_t)(row * G1_STRIDE + ko) * 2,                  \
                 Ag + (size_t)row * 1024 + (kglob) + ko);                     \
        }                                                                     \
        _Pragma("unroll")                                                     \
        for (int r = 0; r < 2; ++r) {                                         \
            const int idx = r * 256 + tid;                                    \
            const int row = idx >> 3, ko = (idx & 7) << 3;                    \
            CP16(_sb + (uint32_t)(G1_A_ELEMS + row * G1_STRIDE + ko) * 2,     \
                 Bg + (size_t)row * 1024 + (kglob) + ko);                     \
        }                                                                     \
    } while (0)

    const int NK = 16;                     // 1024 / 64
    G1_LOAD_STAGE(0, 0);   CP_COMMIT();
    G1_LOAD_STAGE(1, 64);  CP_COMMIT();

    Frag f;
#pragma unroll
    for (int mi = 0; mi < 2; ++mi)
#pragma unroll
        for (int ni = 0; ni < 4; ++ni)
#pragma unroll
            for (int r = 0; r < 4; ++r) f.c[mi][ni][r] = 0.f;

    int rs = 0, ws = 2;                     // read slot, write slot (mod 3)
    for (int kk = 0; kk < NK; ++kk) {
        CP_WAIT(1);                         // stage kk landed
        __syncthreads();                    // all warps done reading slot ws
        if (kk + 2 < NK) G1_LOAD_STAGE(ws, (kk + 2) * 64);
        CP_COMMIT();                        // unconditional: keeps numbering
        const __half* As = sm + rs * G1_STAGE_ELEMS;
        const __half* Bs = As + G1_A_ELEMS;
        KTile t0, t1;
        ld_ktile<G1_STRIDE>(t0, As, Bs, wm, wn, lane, 0);
        ld_ktile<G1_STRIDE>(t1, As, Bs, wm, wn, lane, 16);
        mma_ktile(t0, f);
        ld_ktile<G1_STRIDE>(t0, As, Bs, wm, wn, lane, 32);
        mma_ktile(t1, f);
        ld_ktile<G1_STRIDE>(t1, As, Bs, wm, wn, lane, 48);
        mma_ktile(t0, f);
        mma_ktile(t1, f);
        rs = rs == 2 ? 0 : rs + 1;
        ws = ws == 2 ? 0 : ws + 1;
    }

    // epilogue: fp32 accum -> fp16 -> R1[he][m][d]
#pragma unroll
    for (int mi = 0; mi < 2; ++mi)
#pragma unroll
        for (int ni = 0; ni < 4; ++ni)
#pragma unroll
            for (int r = 0; r < 2; ++r) {
                const int m = m0 + wm + mi * 16 + (lane >> 2) + r * 8;
                const int n = n0 + wn + ni * 8 + ((lane & 3) << 1);
                __half2 h;
                h.x = __float2half_rn(f.c[mi][ni][r * 2]);
                h.y = __float2half_rn(f.c[mi][ni][r * 2 + 1]);
                const int he = n >> 6, d = n & 63;
                *(__half2*)(Rc + ((size_t)(he * 2048 + m)) * 64 + d) = h;
            }
}

// ===================== GEMM2: banded score, diagonal form ===================
// out[g, i, i+c] = sum_d Q1[g,i,d] . R1[he, 1023+c, d]   (K=64)
// CTA tile 128(i) x 64(c), K fully smem-resident, one cp.async burst, one
// barrier, 4-slice reg-double-buffered MMA burst; epilogue STAGES the tile in
// smem (reusing operand space) and emits fully-coalesced per-row spans.
#define G2_STRIDE 72                // 64 + 8 pad (144B, cf-free ldmatrix)
#define G2_A_ELEMS (128 * G2_STRIDE)  // 9216
#define G2_B_ELEMS (64 * G2_STRIDE)   // 4608
#define G2_OP_BYTES ((G2_A_ELEMS + G2_B_ELEMS) * 2)     // 27648
#define G2_STG_STRIDE 66              // floats per staged row (pad 2)
#define G2_STG_BYTES (128 * G2_STG_STRIDE * 4)          // 33792
#define G2_SMEM_BYTES (G2_STG_BYTES)                    // max(27648, 33792)

__global__ __launch_bounds__(256) void gemm2_mma(float* __restrict__ out) {
    extern __shared__ __half sm[];
    const int tid = threadIdx.x, lane = tid & 31, wid = tid >> 5;
    const int wm = (wid >> 1) << 5, wn = (wid & 1) << 5;
    const int g = blockIdx.z, he = g >> 1;
    const int i0 = blockIdx.y << 7;
    const int c0 = (int)blockIdx.x * 64 - i0 - 128;   // disjoint 64-wide c tiles
    const int t0 = 1023 + c0;

    const __half* Ag = (const __half*)g_Q1 + ((size_t)(g << 10) + i0) * 64;
    const __half* Bg = (const __half*)g_R1 + (size_t)he * 2048 * 64;

    const uint32_t smA = smem_u32(sm);

    // load A 128x64 (4 iters) + B 64x64 (2 iters); 8 chunks of 8 per row
#pragma unroll
    for (int r = 0; r < 4; ++r) {
        const int idx = r * 256 + tid;
        const int row = idx >> 3, ko = (idx & 7) << 3;
        CP16(smA + (uint32_t)(row * G2_STRIDE + ko) * 2,
             Ag + (size_t)row * 64 + ko);
    }
#pragma unroll
    for (int r = 0; r < 2; ++r) {
        const int idx = r * 256 + tid;
        const int row = idx >> 3, ko = (idx & 7) << 3;
        int t = t0 + row;                        // clamped rows feed only
        t = t < 0 ? 0 : (t > 2046 ? 2046 : t);   // never-stored columns
        CP16(smA + (uint32_t)(G2_A_ELEMS + row * G2_STRIDE + ko) * 2,
             Bg + (size_t)t * 64 + ko);
    }
    CP_COMMIT();

    Frag f;
#pragma unroll
    for (int mi = 0; mi < 2; ++mi)
#pragma unroll
        for (int ni = 0; ni < 4; ++ni)
#pragma unroll
            for (int r = 0; r < 4; ++r) f.c[mi][ni][r] = 0.f;

    CP_WAIT(0);
    __syncthreads();

    const __half* As = sm;
    const __half* Bs = sm + G2_A_ELEMS;
    KTile t0f, t1f;
    ld_ktile<G2_STRIDE>(t0f, As, Bs, wm, wn, lane, 0);
    ld_ktile<G2_STRIDE>(t1f, As, Bs, wm, wn, lane, 16);
    mma_ktile(t0f, f);
    ld_ktile<G2_STRIDE>(t0f, As, Bs, wm, wn, lane, 32);
    mma_ktile(t1f, f);
    ld_ktile<G2_STRIDE>(t1f, As, Bs, wm, wn, lane, 48);
    mma_ktile(t0f, f);
    mma_ktile(t1f, f);

    // ---- epilogue: stage tile in smem, then coalesced guarded row stores ---
    __syncthreads();                 // all warps done reading operand smem
    float* Sf = (float*)sm;          // reuse as [128][G2_STG_STRIDE] floats
#pragma unroll
    for (int mi = 0; mi < 2; ++mi)
#pragma unroll
        for (int ni = 0; ni < 4; ++ni)
#pragma unroll
            for (int r = 0; r < 2; ++r) {
                const int row = wm + mi * 16 + (lane >> 2) + r * 8;
                const int col = wn + ni * 8 + ((lane & 3) << 1);
                *(float2*)&Sf[row * G2_STG_STRIDE + col] =
                    make_float2(f.c[mi][ni][r * 2], f.c[mi][ni][r * 2 + 1]);
            }
    __syncthreads();

    float* og = out + ((size_t)g << 20);
#pragma unroll
    for (int rr = 0; rr < 16; ++rr) {
        const int row = (wid << 4) + rr;
        const int i = i0 + row;
        float* orow = og + ((size_t)i << 10);
        const int j0 = i + c0 + (lane << 1);     // this lane's first j
        const float2 v = *(const float2*)&Sf[row * G2_STG_STRIDE + (lane << 1)];
        if (((i + c0) & 1) == 0) {               // row-uniform parity branch
            if ((unsigned)j0 < 1023u) {          // both in range, 8B aligned
                *(float2*)&orow[j0] = v;
            } else {
                if ((unsigned)j0 < 1024u)       orow[j0] = v.x;
                if ((unsigned)(j0 + 1) < 1024u) orow[j0 + 1] = v.y;
            }
        } else {
            if ((unsigned)j0 < 1024u)       orow[j0] = v.x;
            if ((unsigned)(j0 + 1) < 1024u) orow[j0 + 1] = v.y;
        }
    }
}

// ===================== launch ===============================================
extern "C" void kernel_launch(void* const* d_in, const int* in_sizes, int n_in,
                              void* d_out, int out_size) {
    const float* query = (const float*)d_in[0];
    const float* posem = (const float*)d_in[1];
    const float* dense = (const float*)d_in[2];
    float* out = (float*)d_out;
    (void)in_sizes; (void)n_in; (void)out_size;

    cudaFuncSetAttribute(gemm1_mma, cudaFuncAttributeMaxDynamicSharedMemorySize,
                         3 * G1_STAGE_BYTES);
    cudaFuncSetAttribute(gemm2_mma, cudaFuncAttributeMaxDynamicSharedMemorySize,
                         G2_SMEM_BYTES);

    split_pq<<<8192, 256>>>(posem, query);
    split_w<<<dim3(32, 32), dim3(32, 8)>>>(dense);
    gemm1_mma<<<dim3(16, 16), 256, 3 * G1_STAGE_BYTES>>>();
    gemm2_mma<<<dim3(18, 8, 32), 256, G2_SMEM_BYTES>>>(out);
}